// round 3
// baseline (speedup 1.0000x reference)
#include <cuda_runtime.h>

#define NBATCH 16384
#define NN 10
#define NPAIR (NN * NN)
#define BPB 16
#define NTHREADS (BPB * NN)   // 160 threads = 5 warps

// Fused front-end weights: u_i = x_i @ A + ab,  v_j = x_j @ Bm + bb
// where A = Wp @ W1[:16], Bm = Wp @ W1[16:], ab = bp@W1[:16] + b1, bb = bp@W1[16:]
__device__ float g_A[96];
__device__ float g_Bm[96];
__device__ float g_ab[32];
__device__ float g_bb[32];

__global__ void prep_kernel(const float* __restrict__ Wp, const float* __restrict__ bp,
                            const float* __restrict__ W1, const float* __restrict__ b1) {
    int t = threadIdx.x;
    if (t < 96) {
        int r = t >> 5, c = t & 31;
        float a = 0.f, bm = 0.f;
#pragma unroll
        for (int m = 0; m < 16; m++) {
            float w = Wp[r * 16 + m];
            a  = fmaf(w, W1[m * 32 + c], a);
            bm = fmaf(w, W1[(16 + m) * 32 + c], bm);
        }
        g_A[t]  = a;
        g_Bm[t] = bm;
    } else if (t < 128) {
        int c = t - 96;
        float a = b1[c], bm = 0.f;
#pragma unroll
        for (int m = 0; m < 16; m++) {
            float w = bp[m];
            a  = fmaf(w, W1[m * 32 + c], a);
            bm = fmaf(w, W1[(16 + m) * 32 + c], bm);
        }
        g_ab[c] = a;
        g_bb[c] = bm;
    }
}

__device__ __forceinline__ float lrelu(float x) {
    // x>=0: x >= 0.2x ; x<0: 0.2x > x  => fmax(x, 0.2x) == leaky_relu(x, 0.2)
    return fmaxf(x, 0.2f * x);
}

__device__ __forceinline__ unsigned long long pack2(float a, float b) {
    unsigned long long p;
    asm("mov.b64 %0, {%1, %2};" : "=l"(p)
        : "r"(__float_as_uint(a)), "r"(__float_as_uint(b)));
    return p;
}

// Process KCNT (even) pair slots [KSTART, KSTART+KCNT) for row (batch, i).
// Two pairs are packed per f32x2 lane; W2 row loads are amortized across all
// KCNT pairs by keeping the c-loop outermost.
template <int KSTART, int KCNT>
__device__ __forceinline__ void pair_block(
    int i, int vbase,
    const float* __restrict__ u,                 // [32] in registers
    const float* __restrict__ vT,                // [32][NTHREADS] smem
    const unsigned long long* __restrict__ W2d,  // [32][8] smem, duplicated f32x2
    const unsigned long long* __restrict__ b2d,  // [8] smem, duplicated f32x2
    const float* __restrict__ W3s,               // [16] smem
    const float* __restrict__ b3s,               // [2] smem
    float* __restrict__ edge_out,
    float* __restrict__ adj_out,
    int wadj)
{
    constexpr int NG = KCNT / 2;

    int col[KCNT];
#pragma unroll
    for (int t = 0; t < KCNT; t++) {
        int k = KSTART + t;
        // idx[i,0] = i ; idx[i,k>=1] = (k-1) if (k-1) < i else k
        int j = (k == 0) ? i : ((k - 1 < i) ? (k - 1) : k);
        col[t] = vbase + j;
    }

    unsigned long long acc[NG][8];
#pragma unroll
    for (int g = 0; g < NG; g++)
#pragma unroll
        for (int q = 0; q < 8; q++)
            acc[g][q] = b2d[q];

#pragma unroll
    for (int c = 0; c < 32; c++) {
        unsigned long long w[8];
#pragma unroll
        for (int q = 0; q < 8; q++) w[q] = W2d[c * 8 + q];
        const float* vrow = vT + c * NTHREADS;
        float uc = u[c];
#pragma unroll
        for (int g = 0; g < NG; g++) {
            float sA = lrelu(uc + vrow[col[2 * g]]);
            float sB = lrelu(uc + vrow[col[2 * g + 1]]);
            unsigned long long h = pack2(sA, sB);
#pragma unroll
            for (int q = 0; q < 8; q++)
                asm("fma.rn.f32x2 %0, %1, %2, %0;"
                    : "+l"(acc[g][q]) : "l"(h), "l"(w[q]));
        }
    }

#pragma unroll
    for (int g = 0; g < NG; g++) {
        float e0A = b3s[0], e1A = b3s[1], e0B = b3s[0], e1B = b3s[1];
#pragma unroll
        for (int q = 0; q < 8; q++) {
            unsigned int ua, ub;
            asm("mov.b64 {%0, %1}, %2;" : "=r"(ua), "=r"(ub) : "l"(acc[g][q]));
            float hA = lrelu(__uint_as_float(ua));
            float hB = lrelu(__uint_as_float(ub));
            e0A = fmaf(hA, W3s[2 * q],     e0A);
            e1A = fmaf(hA, W3s[2 * q + 1], e1A);
            e0B = fmaf(hB, W3s[2 * q],     e0B);
            e1B = fmaf(hB, W3s[2 * q + 1], e1B);
        }
        int k = KSTART + 2 * g;
        float4 ev;
        ev.x = e0A; ev.y = e1A; ev.z = e0B; ev.w = e1B;
        *reinterpret_cast<float4*>(edge_out + 2 * k) = ev;
        if (wadj) {
            float2 av;
            av.x = (e1A > e0A) ? 1.f : 0.f;   // argmax of 2; ties -> index 0
            av.y = (e1B > e0B) ? 1.f : 0.f;
            *reinterpret_cast<float2*>(adj_out + k) = av;
        }
    }
}

__global__ void __launch_bounds__(NTHREADS)
gpn_kernel(const float* __restrict__ pos, const float* __restrict__ ori,
           const float* __restrict__ W2, const float* __restrict__ b2,
           const float* __restrict__ W3, const float* __restrict__ b3,
           float* __restrict__ out, int wadj)
{
    __shared__ float vT[32 * NTHREADS];          // v transposed: [c][node]
    __shared__ unsigned long long W2d[32 * 8];   // duplicated f32x2
    __shared__ unsigned long long b2d[8];
    __shared__ float W3s[16];
    __shared__ float b3s[2];
    __shared__ float wA[96], wB[96], wab[32], wbb[32];

    int tid = threadIdx.x;

    // Stage fused weights
    if (tid < 96) { wA[tid] = g_A[tid]; wB[tid] = g_Bm[tid]; }
    else if (tid < 128) { int c = tid - 96; wab[c] = g_ab[c]; wbb[c] = g_bb[c]; }
    for (int idx = tid; idx < 256; idx += NTHREADS) {
        float w = W2[idx];
        W2d[idx] = pack2(w, w);
    }
    if (tid < 8)  { float w = b2[tid]; b2d[tid] = pack2(w, w); }
    if (tid < 16) W3s[tid] = W3[tid];
    if (tid < 2)  b3s[tid] = b3[tid];
    __syncthreads();

    // Phase 1: per-node u (registers) and v (smem, transposed)
    int bb = tid / NN;
    int i  = tid - bb * NN;
    int gb = blockIdx.x * BPB + bb;
    int node = gb * NN + i;
    float x0 = pos[node * 2 + 0];
    float x1 = pos[node * 2 + 1];
    float x2 = ori[node];

    float u[32];
#pragma unroll
    for (int c = 0; c < 32; c++) {
        u[c] = fmaf(x0, wA[c], fmaf(x1, wA[32 + c], fmaf(x2, wA[64 + c], wab[c])));
        float v = fmaf(x0, wB[c], fmaf(x1, wB[32 + c], fmaf(x2, wB[64 + c], wbb[c])));
        vT[c * NTHREADS + tid] = v;
    }
    __syncthreads();

    // Phase 2: this thread owns row (batch gb, node i) -> 10 pair slots
    int vbase = bb * NN;
    size_t row = (size_t)node * NN;  // = (gb*100 + i*10)
    float* edge_out = out + row * 2;
    float* adj_out  = out + (size_t)NBATCH * NPAIR * 2 + row;

    pair_block<0, 6>(i, vbase, u, vT, W2d, b2d, W3s, b3s, edge_out, adj_out, wadj);
    pair_block<6, 4>(i, vbase, u, vT, W2d, b2d, W3s, b3s, edge_out, adj_out, wadj);
}

extern "C" void kernel_launch(void* const* d_in, const int* in_sizes, int n_in,
                              void* d_out, int out_size) {
    const float* pos = (const float*)d_in[0];   // (B, N, 2)
    const float* ori = (const float*)d_in[1];   // (B, N, 1)
    const float* Wp  = (const float*)d_in[2];   // (3, 16)
    const float* bp  = (const float*)d_in[3];   // (16,)
    const float* W1  = (const float*)d_in[4];   // (32, 32)
    const float* b1  = (const float*)d_in[5];   // (32,)
    const float* W2  = (const float*)d_in[6];   // (32, 8)
    const float* b2  = (const float*)d_in[7];   // (8,)
    const float* W3  = (const float*)d_in[8];   // (8, 2)
    const float* b3  = (const float*)d_in[9];   // (2,)
    float* out = (float*)d_out;

    // Write adjacency section only if the output buffer actually holds it
    // (big_edge: B*N*N*2 floats, adjacency: B*N*N values appended).
    int wadj = (out_size >= NBATCH * NPAIR * 3) ? 1 : 0;

    prep_kernel<<<1, 128>>>(Wp, bp, W1, b1);
    gpn_kernel<<<NBATCH / BPB, NTHREADS>>>(pos, ori, W2, b2, W3, b3, out, wadj);
}

// round 4
// speedup vs baseline: 1.0052x; 1.0052x over previous
#include <cuda_runtime.h>

#define NBATCH 16384
#define NN 10
#define NPAIR (NN * NN)
#define BPB 16
#define NTHREADS (BPB * NN)   // 160 threads = 5 warps

// Fused front-end weights: u_i = x_i @ A + ab,  v_j = x_j @ Bm + bb
// where A = Wp @ W1[:16], Bm = Wp @ W1[16:], ab = bp@W1[:16] + b1, bb = bp@W1[16:]
__device__ float g_A[96];
__device__ float g_Bm[96];
__device__ float g_ab[32];
__device__ float g_bb[32];

__global__ void prep_kernel(const float* __restrict__ Wp, const float* __restrict__ bp,
                            const float* __restrict__ W1, const float* __restrict__ b1) {
    int t = threadIdx.x;
    if (t < 96) {
        int r = t >> 5, c = t & 31;
        float a = 0.f, bm = 0.f;
#pragma unroll
        for (int m = 0; m < 16; m++) {
            float w = Wp[r * 16 + m];
            a  = fmaf(w, W1[m * 32 + c], a);
            bm = fmaf(w, W1[(16 + m) * 32 + c], bm);
        }
        g_A[t]  = a;
        g_Bm[t] = bm;
    } else if (t < 128) {
        int c = t - 96;
        float a = b1[c], bm = 0.f;
#pragma unroll
        for (int m = 0; m < 16; m++) {
            float w = bp[m];
            a  = fmaf(w, W1[m * 32 + c], a);
            bm = fmaf(w, W1[(16 + m) * 32 + c], bm);
        }
        g_ab[c] = a;
        g_bb[c] = bm;
    }
}

__device__ __forceinline__ float lrelu(float x) {
    // x>=0: x >= 0.2x ; x<0: 0.2x > x  => fmax(x, 0.2x) == leaky_relu(x, 0.2)
    return fmaxf(x, 0.2f * x);
}

__device__ __forceinline__ unsigned long long pack2(float a, float b) {
    unsigned long long p;
    asm("mov.b64 %0, {%1, %2};" : "=l"(p)
        : "r"(__float_as_uint(a)), "r"(__float_as_uint(b)));
    return p;
}

// Process KCNT (even) pair slots [KSTART, KSTART+KCNT) for row (batch, i).
// Two pairs are packed per f32x2 lane; W2 row loads are amortized across all
// KCNT pairs by keeping the c-loop outermost.
template <int KSTART, int KCNT>
__device__ __forceinline__ void pair_block(
    int i, int vbase,
    const float* __restrict__ u,                 // [32] in registers
    const float* __restrict__ vT,                // [32][NTHREADS] smem
    const unsigned long long* __restrict__ W2d,  // [32][8] smem, duplicated f32x2
    const unsigned long long* __restrict__ b2d,  // [8] smem, duplicated f32x2
    const float* __restrict__ W3s,               // [16] smem
    const float* __restrict__ b3s,               // [2] smem
    float* __restrict__ edge_out,
    float* __restrict__ adj_out,
    int wadj)
{
    constexpr int NG = KCNT / 2;

    int col[KCNT];
#pragma unroll
    for (int t = 0; t < KCNT; t++) {
        int k = KSTART + t;
        // idx[i,0] = i ; idx[i,k>=1] = (k-1) if (k-1) < i else k
        int j = (k == 0) ? i : ((k - 1 < i) ? (k - 1) : k);
        col[t] = vbase + j;
    }

    unsigned long long acc[NG][8];
#pragma unroll
    for (int g = 0; g < NG; g++)
#pragma unroll
        for (int q = 0; q < 8; q++)
            acc[g][q] = b2d[q];

#pragma unroll
    for (int c = 0; c < 32; c++) {
        unsigned long long w[8];
#pragma unroll
        for (int q = 0; q < 8; q++) w[q] = W2d[c * 8 + q];
        const float* vrow = vT + c * NTHREADS;
        float uc = u[c];
#pragma unroll
        for (int g = 0; g < NG; g++) {
            float sA = lrelu(uc + vrow[col[2 * g]]);
            float sB = lrelu(uc + vrow[col[2 * g + 1]]);
            unsigned long long h = pack2(sA, sB);
#pragma unroll
            for (int q = 0; q < 8; q++)
                asm("fma.rn.f32x2 %0, %1, %2, %0;"
                    : "+l"(acc[g][q]) : "l"(h), "l"(w[q]));
        }
    }

#pragma unroll
    for (int g = 0; g < NG; g++) {
        float e0A = b3s[0], e1A = b3s[1], e0B = b3s[0], e1B = b3s[1];
#pragma unroll
        for (int q = 0; q < 8; q++) {
            unsigned int ua, ub;
            asm("mov.b64 {%0, %1}, %2;" : "=r"(ua), "=r"(ub) : "l"(acc[g][q]));
            float hA = lrelu(__uint_as_float(ua));
            float hB = lrelu(__uint_as_float(ub));
            e0A = fmaf(hA, W3s[2 * q],     e0A);
            e1A = fmaf(hA, W3s[2 * q + 1], e1A);
            e0B = fmaf(hB, W3s[2 * q],     e0B);
            e1B = fmaf(hB, W3s[2 * q + 1], e1B);
        }
        int k = KSTART + 2 * g;
        float4 ev;
        ev.x = e0A; ev.y = e1A; ev.z = e0B; ev.w = e1B;
        *reinterpret_cast<float4*>(edge_out + 2 * k) = ev;
        if (wadj) {
            float2 av;
            av.x = (e1A > e0A) ? 1.f : 0.f;   // argmax of 2; ties -> index 0
            av.y = (e1B > e0B) ? 1.f : 0.f;
            *reinterpret_cast<float2*>(adj_out + k) = av;
        }
    }
}

__global__ void __launch_bounds__(NTHREADS)
gpn_kernel(const float* __restrict__ pos, const float* __restrict__ ori,
           const float* __restrict__ W2, const float* __restrict__ b2,
           const float* __restrict__ W3, const float* __restrict__ b3,
           float* __restrict__ out, int wadj)
{
    __shared__ float vT[32 * NTHREADS];          // v transposed: [c][node]
    __shared__ unsigned long long W2d[32 * 8];   // duplicated f32x2
    __shared__ unsigned long long b2d[8];
    __shared__ float W3s[16];
    __shared__ float b3s[2];
    __shared__ float wA[96], wB[96], wab[32], wbb[32];

    int tid = threadIdx.x;

    // Stage fused weights
    if (tid < 96) { wA[tid] = g_A[tid]; wB[tid] = g_Bm[tid]; }
    else if (tid < 128) { int c = tid - 96; wab[c] = g_ab[c]; wbb[c] = g_bb[c]; }
    for (int idx = tid; idx < 256; idx += NTHREADS) {
        float w = W2[idx];
        W2d[idx] = pack2(w, w);
    }
    if (tid < 8)  { float w = b2[tid]; b2d[tid] = pack2(w, w); }
    if (tid < 16) W3s[tid] = W3[tid];
    if (tid < 2)  b3s[tid] = b3[tid];
    __syncthreads();

    // Phase 1: per-node u (registers) and v (smem, transposed)
    int bb = tid / NN;
    int i  = tid - bb * NN;
    int gb = blockIdx.x * BPB + bb;
    int node = gb * NN + i;
    float x0 = pos[node * 2 + 0];
    float x1 = pos[node * 2 + 1];
    float x2 = ori[node];

    float u[32];
#pragma unroll
    for (int c = 0; c < 32; c++) {
        u[c] = fmaf(x0, wA[c], fmaf(x1, wA[32 + c], fmaf(x2, wA[64 + c], wab[c])));
        float v = fmaf(x0, wB[c], fmaf(x1, wB[32 + c], fmaf(x2, wB[64 + c], wbb[c])));
        vT[c * NTHREADS + tid] = v;
    }
    __syncthreads();

    // Phase 2: this thread owns row (batch gb, node i) -> 10 pair slots
    int vbase = bb * NN;
    size_t row = (size_t)node * NN;  // = (gb*100 + i*10)
    float* edge_out = out + row * 2;
    float* adj_out  = out + (size_t)NBATCH * NPAIR * 2 + row;

    pair_block<0, 6>(i, vbase, u, vT, W2d, b2d, W3s, b3s, edge_out, adj_out, wadj);
    pair_block<6, 4>(i, vbase, u, vT, W2d, b2d, W3s, b3s, edge_out, adj_out, wadj);
}

extern "C" void kernel_launch(void* const* d_in, const int* in_sizes, int n_in,
                              void* d_out, int out_size) {
    const float* pos = (const float*)d_in[0];   // (B, N, 2)
    const float* ori = (const float*)d_in[1];   // (B, N, 1)
    const float* Wp  = (const float*)d_in[2];   // (3, 16)
    const float* bp  = (const float*)d_in[3];   // (16,)
    const float* W1  = (const float*)d_in[4];   // (32, 32)
    const float* b1  = (const float*)d_in[5];   // (32,)
    const float* W2  = (const float*)d_in[6];   // (32, 8)
    const float* b2  = (const float*)d_in[7];   // (8,)
    const float* W3  = (const float*)d_in[8];   // (8, 2)
    const float* b3  = (const float*)d_in[9];   // (2,)
    float* out = (float*)d_out;

    // Write adjacency section only if the output buffer actually holds it
    // (big_edge: B*N*N*2 floats, adjacency: B*N*N values appended).
    int wadj = (out_size >= NBATCH * NPAIR * 3) ? 1 : 0;

    prep_kernel<<<1, 128>>>(Wp, bp, W1, b1);
    gpn_kernel<<<NBATCH / BPB, NTHREADS>>>(pos, ori, W2, b2, W3, b3, out, wadj);
}

// round 5
// speedup vs baseline: 1.0077x; 1.0025x over previous
#include <cuda_runtime.h>

#define NBATCH 16384
#define NN 10
#define NPAIR (NN * NN)
#define BPB 16
#define NTHREADS (BPB * NN)   // 160 threads = 5 warps

// Fused front-end weights: u_i = x_i @ A + ab,  v_j = x_j @ Bm + bb
// where A = Wp @ W1[:16], Bm = Wp @ W1[16:], ab = bp@W1[:16] + b1, bb = bp@W1[16:]
__device__ float g_A[96];
__device__ float g_Bm[96];
__device__ float g_ab[32];
__device__ float g_bb[32];

__global__ void prep_kernel(const float* __restrict__ Wp, const float* __restrict__ bp,
                            const float* __restrict__ W1, const float* __restrict__ b1) {
    int t = threadIdx.x;
    if (t < 96) {
        int r = t >> 5, c = t & 31;
        float a = 0.f, bm = 0.f;
#pragma unroll
        for (int m = 0; m < 16; m++) {
            float w = Wp[r * 16 + m];
            a  = fmaf(w, W1[m * 32 + c], a);
            bm = fmaf(w, W1[(16 + m) * 32 + c], bm);
        }
        g_A[t]  = a;
        g_Bm[t] = bm;
    } else if (t < 128) {
        int c = t - 96;
        float a = b1[c], bm = 0.f;
#pragma unroll
        for (int m = 0; m < 16; m++) {
            float w = bp[m];
            a  = fmaf(w, W1[m * 32 + c], a);
            bm = fmaf(w, W1[(16 + m) * 32 + c], bm);
        }
        g_ab[c] = a;
        g_bb[c] = bm;
    }
}

__device__ __forceinline__ float lrelu(float x) {
    // x>=0: x >= 0.2x ; x<0: 0.2x > x  => fmax(x, 0.2x) == leaky_relu(x, 0.2)
    return fmaxf(x, 0.2f * x);
}

__device__ __forceinline__ unsigned long long pack2(float a, float b) {
    unsigned long long p;
    asm("mov.b64 %0, {%1, %2};" : "=l"(p)
        : "r"(__float_as_uint(a)), "r"(__float_as_uint(b)));
    return p;
}

// Process KCNT (even) pair slots [KSTART, KSTART+KCNT) for row (batch, i).
// Two pairs are packed per f32x2 lane; W2 row loads are amortized across all
// KCNT pairs by keeping the c-loop outermost.
template <int KSTART, int KCNT>
__device__ __forceinline__ void pair_block(
    int i, int vbase,
    const float* __restrict__ u,                 // [32] in registers
    const float* __restrict__ vT,                // [32][NTHREADS] smem
    const unsigned long long* __restrict__ W2d,  // [32][8] smem, duplicated f32x2
    const unsigned long long* __restrict__ b2d,  // [8] smem, duplicated f32x2
    const float* __restrict__ W3s,               // [16] smem
    const float* __restrict__ b3s,               // [2] smem
    float* __restrict__ edge_out,
    float* __restrict__ adj_out,
    int wadj)
{
    constexpr int NG = KCNT / 2;

    int col[KCNT];
#pragma unroll
    for (int t = 0; t < KCNT; t++) {
        int k = KSTART + t;
        // idx[i,0] = i ; idx[i,k>=1] = (k-1) if (k-1) < i else k
        int j = (k == 0) ? i : ((k - 1 < i) ? (k - 1) : k);
        col[t] = vbase + j;
    }

    unsigned long long acc[NG][8];
#pragma unroll
    for (int g = 0; g < NG; g++)
#pragma unroll
        for (int q = 0; q < 8; q++)
            acc[g][q] = b2d[q];

#pragma unroll
    for (int c = 0; c < 32; c++) {
        unsigned long long w[8];
#pragma unroll
        for (int q = 0; q < 8; q++) w[q] = W2d[c * 8 + q];
        const float* vrow = vT + c * NTHREADS;
        float uc = u[c];
#pragma unroll
        for (int g = 0; g < NG; g++) {
            float sA = lrelu(uc + vrow[col[2 * g]]);
            float sB = lrelu(uc + vrow[col[2 * g + 1]]);
            unsigned long long h = pack2(sA, sB);
#pragma unroll
            for (int q = 0; q < 8; q++)
                asm("fma.rn.f32x2 %0, %1, %2, %0;"
                    : "+l"(acc[g][q]) : "l"(h), "l"(w[q]));
        }
    }

#pragma unroll
    for (int g = 0; g < NG; g++) {
        float e0A = b3s[0], e1A = b3s[1], e0B = b3s[0], e1B = b3s[1];
#pragma unroll
        for (int q = 0; q < 8; q++) {
            unsigned int ua, ub;
            asm("mov.b64 {%0, %1}, %2;" : "=r"(ua), "=r"(ub) : "l"(acc[g][q]));
            float hA = lrelu(__uint_as_float(ua));
            float hB = lrelu(__uint_as_float(ub));
            e0A = fmaf(hA, W3s[2 * q],     e0A);
            e1A = fmaf(hA, W3s[2 * q + 1], e1A);
            e0B = fmaf(hB, W3s[2 * q],     e0B);
            e1B = fmaf(hB, W3s[2 * q + 1], e1B);
        }
        int k = KSTART + 2 * g;
        float4 ev;
        ev.x = e0A; ev.y = e1A; ev.z = e0B; ev.w = e1B;
        *reinterpret_cast<float4*>(edge_out + 2 * k) = ev;
        if (wadj) {
            float2 av;
            av.x = (e1A > e0A) ? 1.f : 0.f;   // argmax of 2; ties -> index 0
            av.y = (e1B > e0B) ? 1.f : 0.f;
            *reinterpret_cast<float2*>(adj_out + k) = av;
        }
    }
}

__global__ void __launch_bounds__(NTHREADS)
gpn_kernel(const float* __restrict__ pos, const float* __restrict__ ori,
           const float* __restrict__ W2, const float* __restrict__ b2,
           const float* __restrict__ W3, const float* __restrict__ b3,
           float* __restrict__ out, int wadj)
{
    __shared__ float vT[32 * NTHREADS];          // v transposed: [c][node]
    __shared__ unsigned long long W2d[32 * 8];   // duplicated f32x2
    __shared__ unsigned long long b2d[8];
    __shared__ float W3s[16];
    __shared__ float b3s[2];
    __shared__ float wA[96], wB[96], wab[32], wbb[32];

    int tid = threadIdx.x;

    // Stage fused weights
    if (tid < 96) { wA[tid] = g_A[tid]; wB[tid] = g_Bm[tid]; }
    else if (tid < 128) { int c = tid - 96; wab[c] = g_ab[c]; wbb[c] = g_bb[c]; }
    for (int idx = tid; idx < 256; idx += NTHREADS) {
        float w = W2[idx];
        W2d[idx] = pack2(w, w);
    }
    if (tid < 8)  { float w = b2[tid]; b2d[tid] = pack2(w, w); }
    if (tid < 16) W3s[tid] = W3[tid];
    if (tid < 2)  b3s[tid] = b3[tid];
    __syncthreads();

    // Phase 1: per-node u (registers) and v (smem, transposed)
    int bb = tid / NN;
    int i  = tid - bb * NN;
    int gb = blockIdx.x * BPB + bb;
    int node = gb * NN + i;
    float x0 = pos[node * 2 + 0];
    float x1 = pos[node * 2 + 1];
    float x2 = ori[node];

    float u[32];
#pragma unroll
    for (int c = 0; c < 32; c++) {
        u[c] = fmaf(x0, wA[c], fmaf(x1, wA[32 + c], fmaf(x2, wA[64 + c], wab[c])));
        float v = fmaf(x0, wB[c], fmaf(x1, wB[32 + c], fmaf(x2, wB[64 + c], wbb[c])));
        vT[c * NTHREADS + tid] = v;
    }
    __syncthreads();

    // Phase 2: this thread owns row (batch gb, node i) -> 10 pair slots
    int vbase = bb * NN;
    size_t row = (size_t)node * NN;  // = (gb*100 + i*10)
    float* edge_out = out + row * 2;
    float* adj_out  = out + (size_t)NBATCH * NPAIR * 2 + row;

    pair_block<0, 6>(i, vbase, u, vT, W2d, b2d, W3s, b3s, edge_out, adj_out, wadj);
    pair_block<6, 4>(i, vbase, u, vT, W2d, b2d, W3s, b3s, edge_out, adj_out, wadj);
}

extern "C" void kernel_launch(void* const* d_in, const int* in_sizes, int n_in,
                              void* d_out, int out_size) {
    const float* pos = (const float*)d_in[0];   // (B, N, 2)
    const float* ori = (const float*)d_in[1];   // (B, N, 1)
    const float* Wp  = (const float*)d_in[2];   // (3, 16)
    const float* bp  = (const float*)d_in[3];   // (16,)
    const float* W1  = (const float*)d_in[4];   // (32, 32)
    const float* b1  = (const float*)d_in[5];   // (32,)
    const float* W2  = (const float*)d_in[6];   // (32, 8)
    const float* b2  = (const float*)d_in[7];   // (8,)
    const float* W3  = (const float*)d_in[8];   // (8, 2)
    const float* b3  = (const float*)d_in[9];   // (2,)
    float* out = (float*)d_out;

    // Write adjacency section only if the output buffer actually holds it
    // (big_edge: B*N*N*2 floats, adjacency: B*N*N values appended).
    int wadj = (out_size >= NBATCH * NPAIR * 3) ? 1 : 0;

    prep_kernel<<<1, 128>>>(Wp, bp, W1, b1);
    gpn_kernel<<<NBATCH / BPB, NTHREADS>>>(pos, ori, W2, b2, W3, b3, out, wadj);
}

// round 7
// speedup vs baseline: 2.7346x; 2.7137x over previous
#include <cuda_runtime.h>

#define NBATCH 16384
#define NN 10
#define NPAIR (NN * NN)
#define BPB 8                       // batches per block
#define NODES (BPB * NN)            // 80 nodes per block
#define NTHREADS 224                // 7 warps
#define P2_THREADS (BPB * 25)       // 200: 25 threads/batch, 4 pairs each

typedef unsigned long long ull;

// Fused front-end weights: u_i = x_i @ A + ab,  v_j = x_j @ Bm + bb
// where A = Wp @ W1[:16], Bm = Wp @ W1[16:], ab = bp@W1[:16] + b1, bb = bp@W1[16:]
__device__ float g_A[96];
__device__ float g_Bm[96];
__device__ float g_ab[32];
__device__ float g_bb[32];

__global__ void prep_kernel(const float* __restrict__ Wp, const float* __restrict__ bp,
                            const float* __restrict__ W1, const float* __restrict__ b1) {
    int t = threadIdx.x;
    if (t < 96) {
        int r = t >> 5, c = t & 31;
        float a = 0.f, bm = 0.f;
#pragma unroll
        for (int m = 0; m < 16; m++) {
            float w = Wp[r * 16 + m];
            a  = fmaf(w, W1[m * 32 + c], a);
            bm = fmaf(w, W1[(16 + m) * 32 + c], bm);
        }
        g_A[t]  = a;
        g_Bm[t] = bm;
    } else if (t < 128) {
        int c = t - 96;
        float a = b1[c], bm = 0.f;
#pragma unroll
        for (int m = 0; m < 16; m++) {
            float w = bp[m];
            a  = fmaf(w, W1[m * 32 + c], a);
            bm = fmaf(w, W1[(16 + m) * 32 + c], bm);
        }
        g_ab[c] = a;
        g_bb[c] = bm;
    }
}

__device__ __forceinline__ ull pack2(float a, float b) {
    ull p;
    asm("mov.b64 %0, {%1, %2};" : "=l"(p)
        : "r"(__float_as_uint(a)), "r"(__float_as_uint(b)));
    return p;
}
__device__ __forceinline__ void fma2(ull& acc, ull a, ull b) {
    asm("fma.rn.f32x2 %0, %1, %2, %0;" : "+l"(acc) : "l"(a), "l"(b));
}
__device__ __forceinline__ void unpack2(ull p, float& lo, float& hi) {
    unsigned int a, b;
    asm("mov.b64 {%0, %1}, %2;" : "=r"(a), "=r"(b) : "l"(p));
    lo = __uint_as_float(a); hi = __uint_as_float(b);
}
__device__ __forceinline__ float lrelu(float x) { return fmaxf(x, 0.2f * x); }

// idx[i,0] = i ; idx[i,s>=1] = (s-1) if (s-1) < i else s
__device__ __forceinline__ int partner(int i, int k) {
    int s = k % NN;
    return (s == 0) ? i : ((s - 1 < i) ? (s - 1) : s);
}

__global__ void __launch_bounds__(NTHREADS)
gpn_kernel(const float* __restrict__ pos, const float* __restrict__ ori,
           const float* __restrict__ W2, const float* __restrict__ b2,
           const float* __restrict__ W3, const float* __restrict__ b3,
           float* __restrict__ out, int wadj)
{
    __shared__ float us[32 * NODES];     // u, [c][node]                  10240 B
    __shared__ float vs[32 * NODES];     // v, [c][node]                  10240 B
    __shared__ ull   W2d[32 * 8];        // W2 duplicated f32x2            2048 B
    __shared__ ull   b2d[8];
    __shared__ float W3s[16], b3s[2];
    __shared__ float xs0[NODES], xs1[NODES], xs2[NODES];
    __shared__ float wA[96], wB[96], wab[32], wbb[32];

    int t = threadIdx.x;

    // ---- stage weights + node features ----
    if (t < 96)       { wA[t] = g_A[t]; wB[t] = g_Bm[t]; }
    else if (t < 128) { int c = t - 96; wab[c] = g_ab[c]; wbb[c] = g_bb[c]; }
    if (t < NODES) {
        int g = blockIdx.x * NODES + t;
        float2 p = reinterpret_cast<const float2*>(pos)[g];
        xs0[t] = p.x; xs1[t] = p.y; xs2[t] = ori[g];
    }
    for (int i = t; i < 256; i += NTHREADS) { float w = W2[i]; W2d[i] = pack2(w, w); }
    if (t < 8)  { float w = b2[t]; b2d[t] = pack2(w, w); }
    if (t < 16) W3s[t] = W3[t];
    if (t < 2)  b3s[t] = b3[t];
    __syncthreads();

    // ---- phase 1: per-node u and v, transposed [c][node] ----
    for (int idx = t; idx < 32 * NODES; idx += NTHREADS) {
        int node = idx >> 5, c = idx & 31;
        float x0 = xs0[node], x1 = xs1[node], x2 = xs2[node];
        float u = fmaf(x0, wA[c], fmaf(x1, wA[32 + c], fmaf(x2, wA[64 + c], wab[c])));
        float v = fmaf(x0, wB[c], fmaf(x1, wB[32 + c], fmaf(x2, wB[64 + c], wbb[c])));
        us[c * NODES + node] = u;
        vs[c * NODES + node] = v;
    }
    __syncthreads();

    if (t >= P2_THREADS) return;   // no further barriers below

    // ---- phase 2: thread owns 4 pairs (2 f32x2 groups) of one batch ----
    int b  = t / 25;
    int tt = t - b * 25;
    int k0 = 4 * tt;                       // pairs k0..k0+3
    int iA = k0 / NN;
    int iB = (k0 + 2) / NN;
    int uAo = b * NN + iA;
    int uBo = b * NN + iB;
    int vA0 = b * NN + partner(iA, k0);
    int vA1 = b * NN + partner(iA, k0 + 1);
    int vB0 = b * NN + partner(iB, k0 + 2);
    int vB1 = b * NN + partner(iB, k0 + 3);

    ull accA[8], accB[8];
#pragma unroll
    for (int q = 0; q < 8; q++) { accA[q] = b2d[q]; accB[q] = b2d[q]; }

#pragma unroll
    for (int c = 0; c < 32; c++) {
        const float* uc = us + c * NODES;
        const float* vc = vs + c * NODES;
        float uA = uc[uAo], uB = uc[uBo];
        float a0 = uA + vc[vA0];
        float a1 = uA + vc[vA1];
        float a2 = uB + vc[vB0];
        float a3 = uB + vc[vB1];
        ull sA = pack2(lrelu(a0), lrelu(a1));
        ull sB = pack2(lrelu(a2), lrelu(a3));
        const ull* w = W2d + c * 8;
#pragma unroll
        for (int q = 0; q < 8; q++) {
            ull wq = w[q];
            fma2(accA[q], sA, wq);
            fma2(accB[q], sB, wq);
        }
    }

    // ---- epilogue: lrelu, W3 head, argmax, stores ----
    int gp = (blockIdx.x * BPB + b) * NPAIR + k0;   // global pair index (mult of 4)
    float e[4][2];
#pragma unroll
    for (int p = 0; p < 4; p++) { e[p][0] = b3s[0]; e[p][1] = b3s[1]; }
#pragma unroll
    for (int q = 0; q < 8; q++) {
        float h0, h1, h2, h3;
        unpack2(accA[q], h0, h1);
        unpack2(accB[q], h2, h3);
        h0 = lrelu(h0); h1 = lrelu(h1); h2 = lrelu(h2); h3 = lrelu(h3);
        float w0 = W3s[2 * q], w1 = W3s[2 * q + 1];
        e[0][0] = fmaf(h0, w0, e[0][0]); e[0][1] = fmaf(h0, w1, e[0][1]);
        e[1][0] = fmaf(h1, w0, e[1][0]); e[1][1] = fmaf(h1, w1, e[1][1]);
        e[2][0] = fmaf(h2, w0, e[2][0]); e[2][1] = fmaf(h2, w1, e[2][1]);
        e[3][0] = fmaf(h3, w0, e[3][0]); e[3][1] = fmaf(h3, w1, e[3][1]);
    }

    float4 ev0; ev0.x = e[0][0]; ev0.y = e[0][1]; ev0.z = e[1][0]; ev0.w = e[1][1];
    float4 ev1; ev1.x = e[2][0]; ev1.y = e[2][1]; ev1.z = e[3][0]; ev1.w = e[3][1];
    reinterpret_cast<float4*>(out + (size_t)gp * 2)[0] = ev0;
    reinterpret_cast<float4*>(out + (size_t)(gp + 2) * 2)[0] = ev1;

    if (wadj) {
        float4 av;
        av.x = (e[0][1] > e[0][0]) ? 1.f : 0.f;   // argmax of 2; ties -> 0
        av.y = (e[1][1] > e[1][0]) ? 1.f : 0.f;
        av.z = (e[2][1] > e[2][0]) ? 1.f : 0.f;
        av.w = (e[3][1] > e[3][0]) ? 1.f : 0.f;
        reinterpret_cast<float4*>(out + (size_t)NBATCH * NPAIR * 2 + gp)[0] = av;
    }
}

extern "C" void kernel_launch(void* const* d_in, const int* in_sizes, int n_in,
                              void* d_out, int out_size) {
    const float* pos = (const float*)d_in[0];   // (B, N, 2)
    const float* ori = (const float*)d_in[1];   // (B, N, 1)
    const float* Wp  = (const float*)d_in[2];   // (3, 16)
    const float* bp  = (const float*)d_in[3];   // (16,)
    const float* W1  = (const float*)d_in[4];   // (32, 32)
    const float* b1  = (const float*)d_in[5];   // (32,)
    const float* W2  = (const float*)d_in[6];   // (32, 8)
    const float* b2  = (const float*)d_in[7];   // (8,)
    const float* W3  = (const float*)d_in[8];   // (8, 2)
    const float* b3  = (const float*)d_in[9];   // (2,)
    float* out = (float*)d_out;

    int wadj = (out_size >= NBATCH * NPAIR * 3) ? 1 : 0;

    prep_kernel<<<1, 128>>>(Wp, bp, W1, b1);
    gpn_kernel<<<NBATCH / BPB, NTHREADS>>>(pos, ori, W2, b2, W3, b3, out, wadj);
}

// round 8
// speedup vs baseline: 2.9706x; 1.0863x over previous
#include <cuda_runtime.h>

#define NBATCH 16384
#define NN 10
#define NPAIR (NN * NN)
#define BPB 16                      // batches per block
#define NTHREADS (BPB * NN)         // 160 threads = 5 warps; 1 thread = 1 node = 1 row
#define VSTRIDE 12                  // padded per-batch v stride (float4 alignment)

typedef unsigned long long ull;

// Fused front-end weights: u_i = x_i @ A + ab,  v_j = x_j @ Bm + bb
// where A = Wp @ W1[:16], Bm = Wp @ W1[16:], ab = bp@W1[:16] + b1, bb = bp@W1[16:]
__device__ float g_A[96];
__device__ float g_Bm[96];
__device__ float g_ab[32];
__device__ float g_bb[32];

__global__ void prep_kernel(const float* __restrict__ Wp, const float* __restrict__ bp,
                            const float* __restrict__ W1, const float* __restrict__ b1) {
    int t = threadIdx.x;
    if (t < 96) {
        int r = t >> 5, c = t & 31;
        float a = 0.f, bm = 0.f;
#pragma unroll
        for (int m = 0; m < 16; m++) {
            float w = Wp[r * 16 + m];
            a  = fmaf(w, W1[m * 32 + c], a);
            bm = fmaf(w, W1[(16 + m) * 32 + c], bm);
        }
        g_A[t]  = a;
        g_Bm[t] = bm;
    } else if (t < 128) {
        int c = t - 96;
        float a = b1[c], bm = 0.f;
#pragma unroll
        for (int m = 0; m < 16; m++) {
            float w = bp[m];
            a  = fmaf(w, W1[m * 32 + c], a);
            bm = fmaf(w, W1[(16 + m) * 32 + c], bm);
        }
        g_ab[c] = a;
        g_bb[c] = bm;
    }
}

__device__ __forceinline__ ull pack2(float a, float b) {
    ull p;
    asm("mov.b64 %0, {%1, %2};" : "=l"(p)
        : "r"(__float_as_uint(a)), "r"(__float_as_uint(b)));
    return p;
}
__device__ __forceinline__ ull add2(ull a, ull b) {
    ull r; asm("add.rn.f32x2 %0, %1, %2;" : "=l"(r) : "l"(a), "l"(b)); return r;
}
__device__ __forceinline__ ull mul2(ull a, ull b) {
    ull r; asm("mul.rn.f32x2 %0, %1, %2;" : "=l"(r) : "l"(a), "l"(b)); return r;
}
__device__ __forceinline__ void fma2(ull& acc, ull a, ull b) {
    asm("fma.rn.f32x2 %0, %1, %2, %0;" : "+l"(acc) : "l"(a), "l"(b));
}
__device__ __forceinline__ void unpack2(ull p, float& lo, float& hi) {
    unsigned int a, b;
    asm("mov.b64 {%0, %1}, %2;" : "=r"(a), "=r"(b) : "l"(p));
    lo = __uint_as_float(a); hi = __uint_as_float(b);
}
__device__ __forceinline__ float lrelu(float x) { return fmaxf(x, 0.2f * x); }

__global__ void __launch_bounds__(NTHREADS, 3)
gpn_kernel(const float* __restrict__ pos, const float* __restrict__ ori,
           const float* __restrict__ W2, const float* __restrict__ b2,
           const float* __restrict__ W3, const float* __restrict__ b3,
           float* __restrict__ out, int wadj)
{
    __shared__ float us[32 * NTHREADS];          // u, [c][node]            20480 B
    __shared__ float vs[32 * BPB * VSTRIDE];     // v, [c][b*12 + j]        24576 B
    __shared__ ull   W2d[32 * 8];                // W2 duplicated f32x2      2048 B
    __shared__ ull   b2d[8];
    __shared__ float W3s[16], b3s[2];
    __shared__ float wA[96], wB[96], wab[32], wbb[32];

    int t = threadIdx.x;

    // ---- stage fused weights ----
    if (t < 96)       { wA[t] = g_A[t]; wB[t] = g_Bm[t]; }
    else if (t < 128) { int c = t - 96; wab[c] = g_ab[c]; wbb[c] = g_bb[c]; }
    for (int i0 = t; i0 < 256; i0 += NTHREADS) { float w = W2[i0]; W2d[i0] = pack2(w, w); }
    if (t < 8)  { float w = b2[t]; b2d[t] = pack2(w, w); }
    if (t < 16) W3s[t] = W3[t];
    if (t < 2)  b3s[t] = b3[t];
    __syncthreads();

    // ---- phase 1: thread t owns node t; write u and v transposed ----
    int b = t / NN;
    int i = t - b * NN;
    int gnode = blockIdx.x * NTHREADS + t;
    float2 p = reinterpret_cast<const float2*>(pos)[gnode];
    float x2 = ori[gnode];
    int vcol = b * VSTRIDE + i;
#pragma unroll
    for (int c = 0; c < 32; c++) {
        us[c * NTHREADS + t] =
            fmaf(p.x, wA[c], fmaf(p.y, wA[32 + c], fmaf(x2, wA[64 + c], wab[c])));
        vs[c * (BPB * VSTRIDE) + vcol] =
            fmaf(p.x, wB[c], fmaf(p.y, wB[32 + c], fmaf(x2, wB[64 + c], wbb[c])));
    }
    __syncthreads();

    // ---- phase 2: thread owns row (b, i): all 10 partners, j-ordered ----
    const ull K02 = 0x3E4CCCCD3E4CCCCDULL;  // (0.2f, 0.2f)

    ull acc[5][8];
#pragma unroll
    for (int g = 0; g < 5; g++)
#pragma unroll
        for (int q = 0; q < 8; q++)
            acc[g][q] = b2d[q];

    const float* usp = us + t;
    const char*  vsp = (const char*)(vs + b * VSTRIDE);

#pragma unroll 8
    for (int c = 0; c < 32; c++) {
        float u = usp[c * NTHREADS];
        ull uu = pack2(u, u);
        // v[j] for j=0..9, contiguous & 16B-aligned: 2x LDS.128 + 1x LDS.64
        const char* vrow = vsp + c * (BPB * VSTRIDE * 4);
        ulonglong2 v01 = *reinterpret_cast<const ulonglong2*>(vrow);
        ulonglong2 v23 = *reinterpret_cast<const ulonglong2*>(vrow + 16);
        ull        v4  = *reinterpret_cast<const ull*>(vrow + 32);
        ull vp[5] = { v01.x, v01.y, v23.x, v23.y, v4 };

        ull s[5];
#pragma unroll
        for (int g = 0; g < 5; g++) {
            ull t2 = add2(uu, vp[g]);
            ull m  = mul2(t2, K02);
            float t0, t1, m0, m1;
            unpack2(t2, t0, t1);
            unpack2(m,  m0, m1);
            s[g] = pack2(fmaxf(t0, m0), fmaxf(t1, m1));
        }

        const ull* w = W2d + c * 8;
#pragma unroll
        for (int q = 0; q < 8; q++) {
            ull wq = w[q];
#pragma unroll
            for (int g = 0; g < 5; g++)
                fma2(acc[g][q], s[g], wq);
        }
    }

    // ---- epilogue: per pair j, W3 head + argmax, scatter to slot s(j) ----
    // row base in output: (global batch * 100 + i * 10)
    size_t rowbase = (size_t)(blockIdx.x * BPB + b) * NPAIR + (size_t)i * NN;
    float* edge = out + rowbase * 2;
    float* adj  = out + (size_t)NBATCH * NPAIR * 2 + rowbase;

#pragma unroll
    for (int g = 0; g < 5; g++) {
        float eA0 = b3s[0], eA1 = b3s[1], eB0 = b3s[0], eB1 = b3s[1];
#pragma unroll
        for (int q = 0; q < 8; q++) {
            float h0, h1;
            unpack2(acc[g][q], h0, h1);
            h0 = lrelu(h0); h1 = lrelu(h1);
            float w0 = W3s[2 * q], w1 = W3s[2 * q + 1];
            eA0 = fmaf(h0, w0, eA0); eA1 = fmaf(h0, w1, eA1);
            eB0 = fmaf(h1, w0, eB0); eB1 = fmaf(h1, w1, eB1);
        }
        int j0 = 2 * g, j1 = 2 * g + 1;
        int s0 = (j0 == i) ? 0 : ((j0 < i) ? j0 + 1 : j0);
        int s1 = (j1 == i) ? 0 : ((j1 < i) ? j1 + 1 : j1);
        float2 e0; e0.x = eA0; e0.y = eA1;
        float2 e1; e1.x = eB0; e1.y = eB1;
        reinterpret_cast<float2*>(edge)[s0] = e0;
        reinterpret_cast<float2*>(edge)[s1] = e1;
        if (wadj) {
            adj[s0] = (eA1 > eA0) ? 1.f : 0.f;   // argmax of 2; ties -> 0
            adj[s1] = (eB1 > eB0) ? 1.f : 0.f;
        }
    }
}

extern "C" void kernel_launch(void* const* d_in, const int* in_sizes, int n_in,
                              void* d_out, int out_size) {
    const float* pos = (const float*)d_in[0];   // (B, N, 2)
    const float* ori = (const float*)d_in[1];   // (B, N, 1)
    const float* Wp  = (const float*)d_in[2];   // (3, 16)
    const float* bp  = (const float*)d_in[3];   // (16,)
    const float* W1  = (const float*)d_in[4];   // (32, 32)
    const float* b1  = (const float*)d_in[5];   // (32,)
    const float* W2  = (const float*)d_in[6];   // (32, 8)
    const float* b2  = (const float*)d_in[7];   // (8,)
    const float* W3  = (const float*)d_in[8];   // (8, 2)
    const float* b3  = (const float*)d_in[9];   // (2,)
    float* out = (float*)d_out;

    int wadj = (out_size >= NBATCH * NPAIR * 3) ? 1 : 0;

    prep_kernel<<<1, 128>>>(Wp, bp, W1, b1);
    gpn_kernel<<<NBATCH / BPB, NTHREADS>>>(pos, ori, W2, b2, W3, b3, out, wadj);
}

// round 9
// speedup vs baseline: 3.0129x; 1.0142x over previous
#include <cuda_runtime.h>

#define NBATCH 16384
#define NN 10
#define NPAIR (NN * NN)
#define BPB 8                        // batches per block
#define ROWS (BPB * NN)              // 80 rows per block
#define NTHREADS (2 * ROWS)          // 160 threads: 2 lanes per row (q-split)
#define VSTRIDE 12                   // padded per-batch v stride (float4 alignment)

typedef unsigned long long ull;

// Fused front-end weights: u_i = x_i @ A + ab,  v_j = x_j @ Bm + bb
// where A = Wp @ W1[:16], Bm = Wp @ W1[16:], ab = bp@W1[:16] + b1, bb = bp@W1[16:]
__device__ float g_A[96];
__device__ float g_Bm[96];
__device__ float g_ab[32];
__device__ float g_bb[32];

__global__ void prep_kernel(const float* __restrict__ Wp, const float* __restrict__ bp,
                            const float* __restrict__ W1, const float* __restrict__ b1) {
    int t = threadIdx.x;
    if (t < 96) {
        int r = t >> 5, c = t & 31;
        float a = 0.f, bm = 0.f;
#pragma unroll
        for (int m = 0; m < 16; m++) {
            float w = Wp[r * 16 + m];
            a  = fmaf(w, W1[m * 32 + c], a);
            bm = fmaf(w, W1[(16 + m) * 32 + c], bm);
        }
        g_A[t]  = a;
        g_Bm[t] = bm;
    } else if (t < 128) {
        int c = t - 96;
        float a = b1[c], bm = 0.f;
#pragma unroll
        for (int m = 0; m < 16; m++) {
            float w = bp[m];
            a  = fmaf(w, W1[m * 32 + c], a);
            bm = fmaf(w, W1[(16 + m) * 32 + c], bm);
        }
        g_ab[c] = a;
        g_bb[c] = bm;
    }
}

__device__ __forceinline__ ull pack2(float a, float b) {
    ull p;
    asm("mov.b64 %0, {%1, %2};" : "=l"(p)
        : "r"(__float_as_uint(a)), "r"(__float_as_uint(b)));
    return p;
}
__device__ __forceinline__ ull add2(ull a, ull b) {
    ull r; asm("add.rn.f32x2 %0, %1, %2;" : "=l"(r) : "l"(a), "l"(b)); return r;
}
__device__ __forceinline__ ull mul2(ull a, ull b) {
    ull r; asm("mul.rn.f32x2 %0, %1, %2;" : "=l"(r) : "l"(a), "l"(b)); return r;
}
__device__ __forceinline__ void fma2(ull& acc, ull a, ull b) {
    asm("fma.rn.f32x2 %0, %1, %2, %0;" : "+l"(acc) : "l"(a), "l"(b));
}
__device__ __forceinline__ void unpack2(ull p, float& lo, float& hi) {
    unsigned int a, b;
    asm("mov.b64 {%0, %1}, %2;" : "=r"(a), "=r"(b) : "l"(p));
    lo = __uint_as_float(a); hi = __uint_as_float(b);
}
__device__ __forceinline__ float lrelu(float x) { return fmaxf(x, 0.2f * x); }

__global__ void __launch_bounds__(NTHREADS, 5)
gpn_kernel(const float* __restrict__ pos, const float* __restrict__ ori,
           const float* __restrict__ W2, const float* __restrict__ b2,
           const float* __restrict__ W3, const float* __restrict__ b3,
           float* __restrict__ out, int wadj)
{
    __shared__ float us[32 * ROWS];              // u, [c][row]             10240 B
    __shared__ float vs[32 * BPB * VSTRIDE];     // v, [c][b*12 + j]        12288 B
    __shared__ ull   W2d[32 * 8];                // W2 duplicated f32x2      2048 B
    __shared__ ull   b2d[8];
    __shared__ float W3s[16], b3s[2];
    __shared__ float xs0[ROWS], xs1[ROWS], xs2[ROWS];
    __shared__ float wA[96], wB[96], wab[32], wbb[32];

    int t = threadIdx.x;

    // ---- stage fused weights + node features ----
    if (t < 96)       { wA[t] = g_A[t]; wB[t] = g_Bm[t]; }
    else if (t < 128) { int c = t - 96; wab[c] = g_ab[c]; wbb[c] = g_bb[c]; }
    if (t < ROWS) {
        int g = blockIdx.x * ROWS + t;
        float2 p = reinterpret_cast<const float2*>(pos)[g];
        xs0[t] = p.x; xs1[t] = p.y; xs2[t] = ori[g];
    }
    for (int i0 = t; i0 < 256; i0 += NTHREADS) { float w = W2[i0]; W2d[i0] = pack2(w, w); }
    if (t < 8)  { float w = b2[t]; b2d[t] = pack2(w, w); }
    if (t < 16) W3s[t] = W3[t];
    if (t < 2)  b3s[t] = b3[t];
    __syncthreads();

    // ---- phase 1: compute u, v transposed; 2560 elems over 160 threads ----
    for (int idx = t; idx < 32 * ROWS; idx += NTHREADS) {
        int c = idx / ROWS, node = idx - c * ROWS;
        float x0 = xs0[node], x1 = xs1[node], x2 = xs2[node];
        int nb = node / NN, ni = node - nb * NN;
        us[c * ROWS + node] =
            fmaf(x0, wA[c], fmaf(x1, wA[32 + c], fmaf(x2, wA[64 + c], wab[c])));
        vs[c * (BPB * VSTRIDE) + nb * VSTRIDE + ni] =
            fmaf(x0, wB[c], fmaf(x1, wB[32 + c], fmaf(x2, wB[64 + c], wbb[c])));
    }
    __syncthreads();

    // ---- phase 2: lanes (2m, 2m+1) co-own row (b, i); each does 4 of 8 q ----
    int row  = t >> 1;            // 0..79
    int half = t & 1;             // q-half: 0 -> q 0..3, 1 -> q 4..7
    int b = row / NN;
    int i = row - b * NN;

    const ull K02 = 0x3E4CCCCD3E4CCCCDULL;  // (0.2f, 0.2f)

    ull acc[5][4];
#pragma unroll
    for (int g = 0; g < 5; g++)
#pragma unroll
        for (int q = 0; q < 4; q++)
            acc[g][q] = b2d[half * 4 + q];

    const float* usp = us + row;
    const char*  vsp = (const char*)(vs + b * VSTRIDE);
    const ull*   w2p = W2d + half * 4;

#pragma unroll 8
    for (int c = 0; c < 32; c++) {
        float u = usp[c * ROWS];                       // broadcast (pair same addr)
        ull uu = pack2(u, u);
        const char* vrow = vsp + c * (BPB * VSTRIDE * 4);
        ulonglong2 v01 = *reinterpret_cast<const ulonglong2*>(vrow);
        ulonglong2 v23 = *reinterpret_cast<const ulonglong2*>(vrow + 16);
        ull        v4  = *reinterpret_cast<const ull*>(vrow + 32);
        ull vp[5] = { v01.x, v01.y, v23.x, v23.y, v4 };

        ull s[5];
#pragma unroll
        for (int g = 0; g < 5; g++) {
            ull t2 = add2(uu, vp[g]);
            ull m  = mul2(t2, K02);
            float t0, t1, m0, m1;
            unpack2(t2, t0, t1);
            unpack2(m,  m0, m1);
            s[g] = pack2(fmaxf(t0, m0), fmaxf(t1, m1));
        }

        const ull* w = w2p + c * 8;
        ull w0 = w[0], w1 = w[1], w2 = w[2], w3 = w[3];
#pragma unroll
        for (int g = 0; g < 5; g++) {
            fma2(acc[g][0], s[g], w0);
            fma2(acc[g][1], s[g], w1);
            fma2(acc[g][2], s[g], w2);
            fma2(acc[g][3], s[g], w3);
        }
    }

    // ---- epilogue: partial W3 head over own 4 q's, butterfly-sum with lane
    //      partner, then each lane stores its j of every group ----
    size_t rowbase = (size_t)(blockIdx.x * BPB + b) * NPAIR + (size_t)i * NN;
    float* edge = out + rowbase * 2;
    float* adj  = out + (size_t)NBATCH * NPAIR * 2 + rowbase;

    const float* w3p = W3s + half * 8;
    float bias0 = (half == 0) ? b3s[0] : 0.f;
    float bias1 = (half == 0) ? b3s[1] : 0.f;

#pragma unroll
    for (int g = 0; g < 5; g++) {
        float eA0 = bias0, eA1 = bias1, eB0 = bias0, eB1 = bias1;
#pragma unroll
        for (int q = 0; q < 4; q++) {
            float h0, h1;
            unpack2(acc[g][q], h0, h1);
            h0 = lrelu(h0); h1 = lrelu(h1);
            float w0 = w3p[2 * q], w1 = w3p[2 * q + 1];
            eA0 = fmaf(h0, w0, eA0); eA1 = fmaf(h0, w1, eA1);
            eB0 = fmaf(h1, w0, eB0); eB1 = fmaf(h1, w1, eB1);
        }
        // complete across the two q-halves (lanes 2m <-> 2m+1)
        eA0 += __shfl_xor_sync(0xFFFFFFFF, eA0, 1);
        eA1 += __shfl_xor_sync(0xFFFFFFFF, eA1, 1);
        eB0 += __shfl_xor_sync(0xFFFFFFFF, eB0, 1);
        eB1 += __shfl_xor_sync(0xFFFFFFFF, eB1, 1);

        // lane half stores pair j = 2g + half at output slot s(j)
        int j  = 2 * g + half;
        int sj = (j == i) ? 0 : ((j < i) ? j + 1 : j);
        float2 ev;
        ev.x = half ? eB0 : eA0;
        ev.y = half ? eB1 : eA1;
        reinterpret_cast<float2*>(edge)[sj] = ev;
        if (wadj)
            adj[sj] = (ev.y > ev.x) ? 1.f : 0.f;   // argmax of 2; ties -> 0
    }
}

extern "C" void kernel_launch(void* const* d_in, const int* in_sizes, int n_in,
                              void* d_out, int out_size) {
    const float* pos = (const float*)d_in[0];   // (B, N, 2)
    const float* ori = (const float*)d_in[1];   // (B, N, 1)
    const float* Wp  = (const float*)d_in[2];   // (3, 16)
    const float* bp  = (const float*)d_in[3];   // (16,)
    const float* W1  = (const float*)d_in[4];   // (32, 32)
    const float* b1  = (const float*)d_in[5];   // (32,)
    const float* W2  = (const float*)d_in[6];   // (32, 8)
    const float* b2  = (const float*)d_in[7];   // (8,)
    const float* W3  = (const float*)d_in[8];   // (8, 2)
    const float* b3  = (const float*)d_in[9];   // (2,)
    float* out = (float*)d_out;

    int wadj = (out_size >= NBATCH * NPAIR * 3) ? 1 : 0;

    prep_kernel<<<1, 128>>>(Wp, bp, W1, b1);
    gpn_kernel<<<NBATCH / BPB, NTHREADS>>>(pos, ori, W2, b2, W3, b3, out, wadj);
}

// round 10
// speedup vs baseline: 3.1209x; 1.0358x over previous
#include <cuda_runtime.h>

#define NBATCH 16384
#define NN 10
#define NPAIR (NN * NN)
#define BPB 8                        // batches per block
#define ROWS (BPB * NN)              // 80 rows per block
#define NTHREADS (2 * ROWS)          // 160 threads: 2 lanes per row (q-split)
#define VSTRIDE 12                   // padded per-batch v stride (float4 alignment)

typedef unsigned long long ull;

// Fused front-end weights: u_i = x_i @ A + ab,  v_j = x_j @ Bm + bb
// where A = Wp @ W1[:16], Bm = Wp @ W1[16:], ab = bp@W1[:16] + b1, bb = bp@W1[16:]
__device__ float g_A[96];
__device__ float g_Bm[96];
__device__ float g_ab[32];
__device__ float g_bb[32];

__global__ void prep_kernel(const float* __restrict__ Wp, const float* __restrict__ bp,
                            const float* __restrict__ W1, const float* __restrict__ b1) {
    int t = threadIdx.x;
    if (t < 96) {
        int r = t >> 5, c = t & 31;
        float a = 0.f, bm = 0.f;
#pragma unroll
        for (int m = 0; m < 16; m++) {
            float w = Wp[r * 16 + m];
            a  = fmaf(w, W1[m * 32 + c], a);
            bm = fmaf(w, W1[(16 + m) * 32 + c], bm);
        }
        g_A[t]  = a;
        g_Bm[t] = bm;
    } else if (t < 128) {
        int c = t - 96;
        float a = b1[c], bm = 0.f;
#pragma unroll
        for (int m = 0; m < 16; m++) {
            float w = bp[m];
            a  = fmaf(w, W1[m * 32 + c], a);
            bm = fmaf(w, W1[(16 + m) * 32 + c], bm);
        }
        g_ab[c] = a;
        g_bb[c] = bm;
    }
}

__device__ __forceinline__ ull pack2(float a, float b) {
    ull p;
    asm("mov.b64 %0, {%1, %2};" : "=l"(p)
        : "r"(__float_as_uint(a)), "r"(__float_as_uint(b)));
    return p;
}
__device__ __forceinline__ ull add2(ull a, ull b) {
    ull r; asm("add.rn.f32x2 %0, %1, %2;" : "=l"(r) : "l"(a), "l"(b)); return r;
}
__device__ __forceinline__ ull mul2(ull a, ull b) {
    ull r; asm("mul.rn.f32x2 %0, %1, %2;" : "=l"(r) : "l"(a), "l"(b)); return r;
}
__device__ __forceinline__ ull fma2r(ull a, ull b, ull c) {
    ull r; asm("fma.rn.f32x2 %0, %1, %2, %3;" : "=l"(r) : "l"(a), "l"(b), "l"(c)); return r;
}
__device__ __forceinline__ void fma2(ull& acc, ull a, ull b) {
    asm("fma.rn.f32x2 %0, %1, %2, %0;" : "+l"(acc) : "l"(a), "l"(b));
}
__device__ __forceinline__ void unpack2(ull p, float& lo, float& hi) {
    unsigned int a, b;
    asm("mov.b64 {%0, %1}, %2;" : "=r"(a), "=r"(b) : "l"(p));
    lo = __uint_as_float(a); hi = __uint_as_float(b);
}
__device__ __forceinline__ float lrelu(float x) { return fmaxf(x, 0.2f * x); }

__global__ void __launch_bounds__(NTHREADS, 5)
gpn_kernel(const float* __restrict__ pos, const float* __restrict__ ori,
           const float* __restrict__ W2, const float* __restrict__ b2,
           const float* __restrict__ W3, const float* __restrict__ b3,
           float* __restrict__ out, int wadj)
{
    __shared__ ull   us[32 * ROWS];              // (u,u) dup, [c][row]     20480 B
    __shared__ float vs[32 * BPB * VSTRIDE];     // v, [c][b*12 + j]        12288 B
    __shared__ ull   W2d[32 * 8];                // W2 duplicated f32x2      2048 B
    __shared__ ull   b2d[8];
    __shared__ float W3s[16], b3s[2];
    __shared__ float xs0[ROWS], xs1[ROWS], xs2[ROWS];
    __shared__ float wA[96], wB[96], wab[32], wbb[32];

    int t = threadIdx.x;

    // ---- stage fused weights + node features ----
    if (t < 96)       { wA[t] = g_A[t]; wB[t] = g_Bm[t]; }
    else if (t < 128) { int c = t - 96; wab[c] = g_ab[c]; wbb[c] = g_bb[c]; }
    if (t < ROWS) {
        int g = blockIdx.x * ROWS + t;
        float2 p = reinterpret_cast<const float2*>(pos)[g];
        xs0[t] = p.x; xs1[t] = p.y; xs2[t] = ori[g];
    }
    for (int i0 = t; i0 < 256; i0 += NTHREADS) { float w = W2[i0]; W2d[i0] = pack2(w, w); }
    if (t < 8)  { float w = b2[t]; b2d[t] = pack2(w, w); }
    if (t < 16) W3s[t] = W3[t];
    if (t < 2)  b3s[t] = b3[t];
    __syncthreads();

    // ---- phase 1: compute u (duplicated) and v transposed ----
    for (int idx = t; idx < 32 * ROWS; idx += NTHREADS) {
        int c = idx / ROWS, node = idx - c * ROWS;
        float x0 = xs0[node], x1 = xs1[node], x2 = xs2[node];
        int nb = node / NN, ni = node - nb * NN;
        float u =
            fmaf(x0, wA[c], fmaf(x1, wA[32 + c], fmaf(x2, wA[64 + c], wab[c])));
        us[c * ROWS + node] = pack2(u, u);
        vs[c * (BPB * VSTRIDE) + nb * VSTRIDE + ni] =
            fmaf(x0, wB[c], fmaf(x1, wB[32 + c], fmaf(x2, wB[64 + c], wbb[c])));
    }
    __syncthreads();

    // ---- phase 2: lanes (2m, 2m+1) co-own row (b, i); each does 4 of 8 q ----
    int row  = t >> 1;            // 0..79
    int half = t & 1;             // q-half: 0 -> q 0..3, 1 -> q 4..7
    int b = row / NN;
    int i = row - b * NN;

    const ull K06 = 0x3F19999A3F19999AULL;  // (0.6f, 0.6f)
    const ull K04 = 0x3ECCCCCD3ECCCCCDULL;  // (0.4f, 0.4f)
    const ull KAB = 0x7FFFFFFF7FFFFFFFULL;  // abs mask

    ull acc[5][4];
#pragma unroll
    for (int g = 0; g < 5; g++)
#pragma unroll
        for (int q = 0; q < 4; q++)
            acc[g][q] = b2d[half * 4 + q];

    const ull*  usp = us + row;
    const char* vsp = (const char*)(vs + b * VSTRIDE);
    const ull*  w2p = W2d + half * 4;

#pragma unroll 8
    for (int c = 0; c < 32; c++) {
        ull uu = usp[c * ROWS];                        // LDS.64, pair-broadcast
        const char* vrow = vsp + c * (BPB * VSTRIDE * 4);
        ulonglong2 v01 = *reinterpret_cast<const ulonglong2*>(vrow);
        ulonglong2 v23 = *reinterpret_cast<const ulonglong2*>(vrow + 16);
        ull        v4  = *reinterpret_cast<const ull*>(vrow + 32);
        ull vp[5] = { v01.x, v01.y, v23.x, v23.y, v4 };

        // lrelu(x) = 0.6x + 0.4|x|  (packed; no unpack/pack, no FMNMX)
        ull s[5];
#pragma unroll
        for (int g = 0; g < 5; g++) {
            ull t2 = add2(uu, vp[g]);
            ull ab = t2 & KAB;
            s[g] = fma2r(t2, K06, mul2(ab, K04));
        }

        const ull* w = w2p + c * 8;
        ull w0 = w[0], w1 = w[1], w2 = w[2], w3 = w[3];
#pragma unroll
        for (int g = 0; g < 5; g++) {
            fma2(acc[g][0], s[g], w0);
            fma2(acc[g][1], s[g], w1);
            fma2(acc[g][2], s[g], w2);
            fma2(acc[g][3], s[g], w3);
        }
    }

    // ---- epilogue: partial W3 head over own 4 q's, butterfly-sum with lane
    //      partner, then each lane stores its j of every group ----
    size_t rowbase = (size_t)(blockIdx.x * BPB + b) * NPAIR + (size_t)i * NN;
    float* edge = out + rowbase * 2;
    float* adj  = out + (size_t)NBATCH * NPAIR * 2 + rowbase;

    const float* w3p = W3s + half * 8;
    float bias0 = (half == 0) ? b3s[0] : 0.f;
    float bias1 = (half == 0) ? b3s[1] : 0.f;

#pragma unroll
    for (int g = 0; g < 5; g++) {
        float eA0 = bias0, eA1 = bias1, eB0 = bias0, eB1 = bias1;
#pragma unroll
        for (int q = 0; q < 4; q++) {
            float h0, h1;
            unpack2(acc[g][q], h0, h1);
            h0 = lrelu(h0); h1 = lrelu(h1);
            float w0 = w3p[2 * q], w1 = w3p[2 * q + 1];
            eA0 = fmaf(h0, w0, eA0); eA1 = fmaf(h0, w1, eA1);
            eB0 = fmaf(h1, w0, eB0); eB1 = fmaf(h1, w1, eB1);
        }
        // complete across the two q-halves (lanes 2m <-> 2m+1)
        eA0 += __shfl_xor_sync(0xFFFFFFFF, eA0, 1);
        eA1 += __shfl_xor_sync(0xFFFFFFFF, eA1, 1);
        eB0 += __shfl_xor_sync(0xFFFFFFFF, eB0, 1);
        eB1 += __shfl_xor_sync(0xFFFFFFFF, eB1, 1);

        // lane half stores pair j = 2g + half at output slot s(j)
        int j  = 2 * g + half;
        int sj = (j == i) ? 0 : ((j < i) ? j + 1 : j);
        float2 ev;
        ev.x = half ? eB0 : eA0;
        ev.y = half ? eB1 : eA1;
        reinterpret_cast<float2*>(edge)[sj] = ev;
        if (wadj)
            adj[sj] = (ev.y > ev.x) ? 1.f : 0.f;   // argmax of 2; ties -> 0
    }
}

extern "C" void kernel_launch(void* const* d_in, const int* in_sizes, int n_in,
                              void* d_out, int out_size) {
    const float* pos = (const float*)d_in[0];   // (B, N, 2)
    const float* ori = (const float*)d_in[1];   // (B, N, 1)
    const float* Wp  = (const float*)d_in[2];   // (3, 16)
    const float* bp  = (const float*)d_in[3];   // (16,)
    const float* W1  = (const float*)d_in[4];   // (32, 32)
    const float* b1  = (const float*)d_in[5];   // (32,)
    const float* W2  = (const float*)d_in[6];   // (32, 8)
    const float* b2  = (const float*)d_in[7];   // (8,)
    const float* W3  = (const float*)d_in[8];   // (8, 2)
    const float* b3  = (const float*)d_in[9];   // (2,)
    float* out = (float*)d_out;

    int wadj = (out_size >= NBATCH * NPAIR * 3) ? 1 : 0;

    prep_kernel<<<1, 128>>>(Wp, bp, W1, b1);
    gpn_kernel<<<NBATCH / BPB, NTHREADS>>>(pos, ori, W2, b2, W3, b3, out, wadj);
}

// round 11
// speedup vs baseline: 3.1452x; 1.0078x over previous
#include <cuda_runtime.h>

#define NBATCH 16384
#define NN 10
#define NPAIR (NN * NN)
#define BPB 8                        // batches per block
#define ROWS (BPB * NN)              // 80 rows per block
#define NTHREADS (2 * ROWS)          // 160 threads: 2 lanes per row (q-split)
#define VSTRIDE 12                   // padded per-batch v stride (float4 alignment)

typedef unsigned long long ull;

// Fused front-end weights: u_i = x_i @ A + ab,  v_j = x_j @ Bm + bb
// where A = Wp @ W1[:16], Bm = Wp @ W1[16:], ab = bp@W1[:16] + b1, bb = bp@W1[16:]
__device__ float g_A[96];
__device__ float g_Bm[96];
__device__ float g_ab[32];
__device__ float g_bb[32];

__global__ void prep_kernel(const float* __restrict__ Wp, const float* __restrict__ bp,
                            const float* __restrict__ W1, const float* __restrict__ b1) {
    int t = threadIdx.x;
    if (t < 96) {
        int r = t >> 5, c = t & 31;
        float a = 0.f, bm = 0.f;
#pragma unroll
        for (int m = 0; m < 16; m++) {
            float w = Wp[r * 16 + m];
            a  = fmaf(w, W1[m * 32 + c], a);
            bm = fmaf(w, W1[(16 + m) * 32 + c], bm);
        }
        g_A[t]  = a;
        g_Bm[t] = bm;
    } else if (t < 128) {
        int c = t - 96;
        float a = b1[c], bm = 0.f;
#pragma unroll
        for (int m = 0; m < 16; m++) {
            float w = bp[m];
            a  = fmaf(w, W1[m * 32 + c], a);
            bm = fmaf(w, W1[(16 + m) * 32 + c], bm);
        }
        g_ab[c] = a;
        g_bb[c] = bm;
    }
}

__device__ __forceinline__ ull pack2(float a, float b) {
    ull p;
    asm("mov.b64 %0, {%1, %2};" : "=l"(p)
        : "r"(__float_as_uint(a)), "r"(__float_as_uint(b)));
    return p;
}
__device__ __forceinline__ ull add2(ull a, ull b) {
    ull r; asm("add.rn.f32x2 %0, %1, %2;" : "=l"(r) : "l"(a), "l"(b)); return r;
}
__device__ __forceinline__ ull fma2r(ull a, ull b, ull c) {
    ull r; asm("fma.rn.f32x2 %0, %1, %2, %3;" : "=l"(r) : "l"(a), "l"(b), "l"(c)); return r;
}
__device__ __forceinline__ void fma2(ull& acc, ull a, ull b) {
    asm("fma.rn.f32x2 %0, %1, %2, %0;" : "+l"(acc) : "l"(a), "l"(b));
}
__device__ __forceinline__ void unpack2(ull p, float& lo, float& hi) {
    unsigned int a, b;
    asm("mov.b64 {%0, %1}, %2;" : "=r"(a), "=r"(b) : "l"(p));
    lo = __uint_as_float(a); hi = __uint_as_float(b);
}
__device__ __forceinline__ float lrelu(float x) { return fmaxf(x, 0.2f * x); }

__global__ void __launch_bounds__(NTHREADS, 6)
gpn_kernel(const float* __restrict__ pos, const float* __restrict__ ori,
           const float* __restrict__ W2, const float* __restrict__ b2,
           const float* __restrict__ W3, const float* __restrict__ b3,
           float* __restrict__ out, int wadj)
{
    __shared__ ull   us[32 * ROWS];              // (u,u) dup, [c][row]     20480 B
    __shared__ float vs[32 * BPB * VSTRIDE];     // v, [c][b*12 + j]        12288 B
    __shared__ ull   W2d[32 * 8];                // 0.4*W2 duplicated f32x2  2048 B
    __shared__ ull   b2d[8];
    __shared__ float W3s[16], b3s[2];
    __shared__ float xs0[ROWS], xs1[ROWS], xs2[ROWS];
    __shared__ float wA[96], wB[96], wab[32], wbb[32];

    int t = threadIdx.x;

    // ---- stage fused weights + node features ----
    if (t < 96)       { wA[t] = g_A[t]; wB[t] = g_Bm[t]; }
    else if (t < 128) { int c = t - 96; wab[c] = g_ab[c]; wbb[c] = g_bb[c]; }
    if (t < ROWS) {
        int g = blockIdx.x * ROWS + t;
        float2 p = reinterpret_cast<const float2*>(pos)[g];
        xs0[t] = p.x; xs1[t] = p.y; xs2[t] = ori[g];
    }
    // W2 pre-scaled by 0.4: lrelu(t) = 0.4*(1.5t + |t|), the 0.4 folds into W2
    for (int i0 = t; i0 < 256; i0 += NTHREADS) {
        float w = 0.4f * W2[i0];
        W2d[i0] = pack2(w, w);
    }
    if (t < 8)  { float w = b2[t]; b2d[t] = pack2(w, w); }
    if (t < 16) W3s[t] = W3[t];
    if (t < 2)  b3s[t] = b3[t];
    __syncthreads();

    // ---- phase 1: compute u (duplicated) and v transposed ----
    for (int idx = t; idx < 32 * ROWS; idx += NTHREADS) {
        int c = idx / ROWS, node = idx - c * ROWS;
        float x0 = xs0[node], x1 = xs1[node], x2 = xs2[node];
        int nb = node / NN, ni = node - nb * NN;
        float u =
            fmaf(x0, wA[c], fmaf(x1, wA[32 + c], fmaf(x2, wA[64 + c], wab[c])));
        us[c * ROWS + node] = pack2(u, u);
        vs[c * (BPB * VSTRIDE) + nb * VSTRIDE + ni] =
            fmaf(x0, wB[c], fmaf(x1, wB[32 + c], fmaf(x2, wB[64 + c], wbb[c])));
    }
    __syncthreads();

    // ---- phase 2: lanes (2m, 2m+1) co-own row (b, i); each does 4 of 8 q ----
    int row  = t >> 1;            // 0..79
    int half = t & 1;             // q-half: 0 -> q 0..3, 1 -> q 4..7
    int b = row / NN;
    int i = row - b * NN;

    const ull K15 = 0x3FC000003FC00000ULL;  // (1.5f, 1.5f)
    const ull KAB = 0x7FFFFFFF7FFFFFFFULL;  // abs mask

    ull acc[5][4];
#pragma unroll
    for (int g = 0; g < 5; g++)
#pragma unroll
        for (int q = 0; q < 4; q++)
            acc[g][q] = b2d[half * 4 + q];

    const ull*  usp = us + row;
    const char* vsp = (const char*)(vs + b * VSTRIDE);
    const ull*  w2p = W2d + half * 4;

#pragma unroll 8
    for (int c = 0; c < 32; c++) {
        ull uu = usp[c * ROWS];                        // LDS.64, pair-broadcast
        const char* vrow = vsp + c * (BPB * VSTRIDE * 4);
        ulonglong2 v01 = *reinterpret_cast<const ulonglong2*>(vrow);
        ulonglong2 v23 = *reinterpret_cast<const ulonglong2*>(vrow + 16);
        ull        v4  = *reinterpret_cast<const ull*>(vrow + 32);
        ull vp[5] = { v01.x, v01.y, v23.x, v23.y, v4 };

        // p = 1.5t + |t| ; lrelu(t)*W2 == p*(0.4*W2)
        ull s[5];
#pragma unroll
        for (int g = 0; g < 5; g++) {
            ull t2 = add2(uu, vp[g]);
            s[g] = fma2r(t2, K15, t2 & KAB);
        }

        const ull* w = w2p + c * 8;
        ull w0 = w[0], w1 = w[1], w2 = w[2], w3 = w[3];
#pragma unroll
        for (int g = 0; g < 5; g++) {
            fma2(acc[g][0], s[g], w0);
            fma2(acc[g][1], s[g], w1);
            fma2(acc[g][2], s[g], w2);
            fma2(acc[g][3], s[g], w3);
        }
    }

    // ---- epilogue: partial W3 head over own 4 q's, butterfly-sum with lane
    //      partner, then each lane stores its j of every group ----
    size_t rowbase = (size_t)(blockIdx.x * BPB + b) * NPAIR + (size_t)i * NN;
    float* edge = out + rowbase * 2;
    float* adj  = out + (size_t)NBATCH * NPAIR * 2 + rowbase;

    const float* w3p = W3s + half * 8;
    float bias0 = (half == 0) ? b3s[0] : 0.f;
    float bias1 = (half == 0) ? b3s[1] : 0.f;

#pragma unroll
    for (int g = 0; g < 5; g++) {
        float eA0 = bias0, eA1 = bias1, eB0 = bias0, eB1 = bias1;
#pragma unroll
        for (int q = 0; q < 4; q++) {
            float h0, h1;
            unpack2(acc[g][q], h0, h1);
            h0 = lrelu(h0); h1 = lrelu(h1);
            float w0 = w3p[2 * q], w1 = w3p[2 * q + 1];
            eA0 = fmaf(h0, w0, eA0); eA1 = fmaf(h0, w1, eA1);
            eB0 = fmaf(h1, w0, eB0); eB1 = fmaf(h1, w1, eB1);
        }
        // complete across the two q-halves (lanes 2m <-> 2m+1)
        eA0 += __shfl_xor_sync(0xFFFFFFFF, eA0, 1);
        eA1 += __shfl_xor_sync(0xFFFFFFFF, eA1, 1);
        eB0 += __shfl_xor_sync(0xFFFFFFFF, eB0, 1);
        eB1 += __shfl_xor_sync(0xFFFFFFFF, eB1, 1);

        // lane half stores pair j = 2g + half at output slot s(j)
        int j  = 2 * g + half;
        int sj = (j == i) ? 0 : ((j < i) ? j + 1 : j);
        float2 ev;
        ev.x = half ? eB0 : eA0;
        ev.y = half ? eB1 : eA1;
        reinterpret_cast<float2*>(edge)[sj] = ev;
        if (wadj)
            adj[sj] = (ev.y > ev.x) ? 1.f : 0.f;   // argmax of 2; ties -> 0
    }
}

extern "C" void kernel_launch(void* const* d_in, const int* in_sizes, int n_in,
                              void* d_out, int out_size) {
    const float* pos = (const float*)d_in[0];   // (B, N, 2)
    const float* ori = (const float*)d_in[1];   // (B, N, 1)
    const float* Wp  = (const float*)d_in[2];   // (3, 16)
    const float* bp  = (const float*)d_in[3];   // (16,)
    const float* W1  = (const float*)d_in[4];   // (32, 32)
    const float* b1  = (const float*)d_in[5];   // (32,)
    const float* W2  = (const float*)d_in[6];   // (32, 8)
    const float* b2  = (const float*)d_in[7];   // (8,)
    const float* W3  = (const float*)d_in[8];   // (8, 2)
    const float* b3  = (const float*)d_in[9];   // (2,)
    float* out = (float*)d_out;

    int wadj = (out_size >= NBATCH * NPAIR * 3) ? 1 : 0;

    prep_kernel<<<1, 128>>>(Wp, bp, W1, b1);
    gpn_kernel<<<NBATCH / BPB, NTHREADS>>>(pos, ori, W2, b2, W3, b3, out, wadj);
}

// round 12
// speedup vs baseline: 3.2654x; 1.0382x over previous
#include <cuda_runtime.h>

#define NBATCH 16384
#define NN 10
#define NPAIR (NN * NN)
#define BPB 8                        // batches per block
#define ROWS (BPB * NN)              // 80 rows per block
#define NTHREADS (2 * ROWS)          // 160 threads: 2 lanes per row (q-split)
#define VSTRIDE 12                   // padded per-batch v stride (float4 alignment)

typedef unsigned long long ull;

// Fused front-end weights: u_i = x_i @ A + ab,  v_j = x_j @ Bm + bb
// where A = Wp @ W1[:16], Bm = Wp @ W1[16:], ab = bp@W1[:16] + b1, bb = bp@W1[16:]
__device__ float g_A[96];
__device__ float g_Bm[96];
__device__ float g_ab[32];
__device__ float g_bb[32];

__global__ void prep_kernel(const float* __restrict__ Wp, const float* __restrict__ bp,
                            const float* __restrict__ W1, const float* __restrict__ b1) {
    int t = threadIdx.x;
    if (t < 96) {
        int r = t >> 5, c = t & 31;
        float a = 0.f, bm = 0.f;
#pragma unroll
        for (int m = 0; m < 16; m++) {
            float w = Wp[r * 16 + m];
            a  = fmaf(w, W1[m * 32 + c], a);
            bm = fmaf(w, W1[(16 + m) * 32 + c], bm);
        }
        g_A[t]  = a;
        g_Bm[t] = bm;
    } else if (t < 128) {
        int c = t - 96;
        float a = b1[c], bm = 0.f;
#pragma unroll
        for (int m = 0; m < 16; m++) {
            float w = bp[m];
            a  = fmaf(w, W1[m * 32 + c], a);
            bm = fmaf(w, W1[(16 + m) * 32 + c], bm);
        }
        g_ab[c] = a;
        g_bb[c] = bm;
    }
}

__device__ __forceinline__ ull pack2(float a, float b) {
    ull p;
    asm("mov.b64 %0, {%1, %2};" : "=l"(p)
        : "r"(__float_as_uint(a)), "r"(__float_as_uint(b)));
    return p;
}
__device__ __forceinline__ ull add2(ull a, ull b) {
    ull r; asm("add.rn.f32x2 %0, %1, %2;" : "=l"(r) : "l"(a), "l"(b)); return r;
}
__device__ __forceinline__ ull fma2r(ull a, ull b, ull c) {
    ull r; asm("fma.rn.f32x2 %0, %1, %2, %3;" : "=l"(r) : "l"(a), "l"(b), "l"(c)); return r;
}
__device__ __forceinline__ void fma2(ull& acc, ull a, ull b) {
    asm("fma.rn.f32x2 %0, %1, %2, %0;" : "+l"(acc) : "l"(a), "l"(b));
}
__device__ __forceinline__ void unpack2(ull p, float& lo, float& hi) {
    unsigned int a, b;
    asm("mov.b64 {%0, %1}, %2;" : "=r"(a), "=r"(b) : "l"(p));
    lo = __uint_as_float(a); hi = __uint_as_float(b);
}
__device__ __forceinline__ float lrelu(float x) { return fmaxf(x, 0.2f * x); }

__global__ void __launch_bounds__(NTHREADS, 5)
gpn_kernel(const float* __restrict__ pos, const float* __restrict__ ori,
           const float* __restrict__ W2, const float* __restrict__ b2,
           const float* __restrict__ W3, const float* __restrict__ b3,
           float* __restrict__ out, int wadj)
{
    __shared__ ull   us[32 * ROWS];              // (u,u) dup, [c][row]     20480 B
    __shared__ float vs[32 * BPB * VSTRIDE];     // v, [c][b*12 + j]        12288 B
    __shared__ ull   W2d[32 * 8];                // 0.4*W2 duplicated f32x2  2048 B
    __shared__ ull   b2d[8];
    __shared__ float W3s[16], b3s[2];
    __shared__ float xs0[ROWS], xs1[ROWS], xs2[ROWS];
    __shared__ float wA[96], wB[96], wab[32], wbb[32];

    int t = threadIdx.x;

    // ---- stage fused weights + node features ----
    if (t < 96)       { wA[t] = g_A[t]; wB[t] = g_Bm[t]; }
    else if (t < 128) { int c = t - 96; wab[c] = g_ab[c]; wbb[c] = g_bb[c]; }
    if (t < ROWS) {
        int g = blockIdx.x * ROWS + t;
        float2 p = reinterpret_cast<const float2*>(pos)[g];
        xs0[t] = p.x; xs1[t] = p.y; xs2[t] = ori[g];
    }
    // W2 pre-scaled by 0.4: lrelu(t) = 0.4*(1.5t + |t|), the 0.4 folds into W2
    for (int i0 = t; i0 < 256; i0 += NTHREADS) {
        float w = 0.4f * W2[i0];
        W2d[i0] = pack2(w, w);
    }
    if (t < 8)  { float w = b2[t]; b2d[t] = pack2(w, w); }
    if (t < 16) W3s[t] = W3[t];
    if (t < 2)  b3s[t] = b3[t];
    __syncthreads();

    // ---- phase 1: compute u (duplicated) and v transposed ----
    for (int idx = t; idx < 32 * ROWS; idx += NTHREADS) {
        int c = idx / ROWS, node = idx - c * ROWS;
        float x0 = xs0[node], x1 = xs1[node], x2 = xs2[node];
        int nb = node / NN, ni = node - nb * NN;
        float u =
            fmaf(x0, wA[c], fmaf(x1, wA[32 + c], fmaf(x2, wA[64 + c], wab[c])));
        us[c * ROWS + node] = pack2(u, u);
        vs[c * (BPB * VSTRIDE) + nb * VSTRIDE + ni] =
            fmaf(x0, wB[c], fmaf(x1, wB[32 + c], fmaf(x2, wB[64 + c], wbb[c])));
    }
    __syncthreads();

    // ---- phase 2: lanes (2m, 2m+1) co-own row (b, i); each does 4 of 8 q ----
    int row  = t >> 1;            // 0..79
    int half = t & 1;             // q-half: 0 -> q 0..3, 1 -> q 4..7
    int b = row / NN;
    int i = row - b * NN;

    const ull K15 = 0x3FC000003FC00000ULL;  // (1.5f, 1.5f)
    const ull KAB = 0x7FFFFFFF7FFFFFFFULL;  // abs mask

    ull acc[5][4];
#pragma unroll
    for (int g = 0; g < 5; g++)
#pragma unroll
        for (int q = 0; q < 4; q++)
            acc[g][q] = b2d[half * 4 + q];

    const ull*  usp = us + row;
    const char* vsp = (const char*)(vs + b * VSTRIDE);
    const ull*  w2p = W2d + half * 4;

    // software-pipelined mainloop: prefetch c+1 while computing c
    ull uu = usp[0];
    ulonglong2 v01 = *reinterpret_cast<const ulonglong2*>(vsp);
    ulonglong2 v23 = *reinterpret_cast<const ulonglong2*>(vsp + 16);
    ull        v4  = *reinterpret_cast<const ull*>(vsp + 32);
    ulonglong2 w01 = *reinterpret_cast<const ulonglong2*>(w2p);
    ulonglong2 w23 = *reinterpret_cast<const ulonglong2*>(w2p + 2);

#pragma unroll
    for (int c = 0; c < 32; c++) {
        ull cuu = uu;
        ull vp[5] = { v01.x, v01.y, v23.x, v23.y, v4 };
        ulonglong2 cw01 = w01, cw23 = w23;

        if (c < 31) {
            uu = usp[(c + 1) * ROWS];
            const char* nv = vsp + (c + 1) * (BPB * VSTRIDE * 4);
            v01 = *reinterpret_cast<const ulonglong2*>(nv);
            v23 = *reinterpret_cast<const ulonglong2*>(nv + 16);
            v4  = *reinterpret_cast<const ull*>(nv + 32);
            const ull* nw = w2p + (c + 1) * 8;
            w01 = *reinterpret_cast<const ulonglong2*>(nw);
            w23 = *reinterpret_cast<const ulonglong2*>(nw + 2);
        }

        // p = 1.5t + |t| ; lrelu(t)*W2 == p*(0.4*W2)
        ull s[5];
#pragma unroll
        for (int g = 0; g < 5; g++) {
            ull t2 = add2(cuu, vp[g]);
            s[g] = fma2r(t2, K15, t2 & KAB);
        }
#pragma unroll
        for (int g = 0; g < 5; g++) {
            fma2(acc[g][0], s[g], cw01.x);
            fma2(acc[g][1], s[g], cw01.y);
            fma2(acc[g][2], s[g], cw23.x);
            fma2(acc[g][3], s[g], cw23.y);
        }
    }

    // ---- epilogue: partial W3 head over own 4 q's, butterfly-sum with lane
    //      partner, then each lane stores its j of every group ----
    size_t rowbase = (size_t)(blockIdx.x * BPB + b) * NPAIR + (size_t)i * NN;
    float* edge = out + rowbase * 2;
    float* adj  = out + (size_t)NBATCH * NPAIR * 2 + rowbase;

    const float* w3p = W3s + half * 8;
    float bias0 = (half == 0) ? b3s[0] : 0.f;
    float bias1 = (half == 0) ? b3s[1] : 0.f;

#pragma unroll
    for (int g = 0; g < 5; g++) {
        float eA0 = bias0, eA1 = bias1, eB0 = bias0, eB1 = bias1;
#pragma unroll
        for (int q = 0; q < 4; q++) {
            float h0, h1;
            unpack2(acc[g][q], h0, h1);
            h0 = lrelu(h0); h1 = lrelu(h1);
            float w0 = w3p[2 * q], w1 = w3p[2 * q + 1];
            eA0 = fmaf(h0, w0, eA0); eA1 = fmaf(h0, w1, eA1);
            eB0 = fmaf(h1, w0, eB0); eB1 = fmaf(h1, w1, eB1);
        }
        // complete across the two q-halves (lanes 2m <-> 2m+1)
        eA0 += __shfl_xor_sync(0xFFFFFFFF, eA0, 1);
        eA1 += __shfl_xor_sync(0xFFFFFFFF, eA1, 1);
        eB0 += __shfl_xor_sync(0xFFFFFFFF, eB0, 1);
        eB1 += __shfl_xor_sync(0xFFFFFFFF, eB1, 1);

        // lane half stores pair j = 2g + half at output slot s(j)
        int j  = 2 * g + half;
        int sj = (j == i) ? 0 : ((j < i) ? j + 1 : j);
        float2 ev;
        ev.x = half ? eB0 : eA0;
        ev.y = half ? eB1 : eA1;
        reinterpret_cast<float2*>(edge)[sj] = ev;
        if (wadj)
            adj[sj] = (ev.y > ev.x) ? 1.f : 0.f;   // argmax of 2; ties -> 0
    }
}

extern "C" void kernel_launch(void* const* d_in, const int* in_sizes, int n_in,
                              void* d_out, int out_size) {
    const float* pos = (const float*)d_in[0];   // (B, N, 2)
    const float* ori = (const float*)d_in[1];   // (B, N, 1)
    const float* Wp  = (const float*)d_in[2];   // (3, 16)
    const float* bp  = (const float*)d_in[3];   // (16,)
    const float* W1  = (const float*)d_in[4];   // (32, 32)
    const float* b1  = (const float*)d_in[5];   // (32,)
    const float* W2  = (const float*)d_in[6];   // (32, 8)
    const float* b2  = (const float*)d_in[7];   // (8,)
    const float* W3  = (const float*)d_in[8];   // (8, 2)
    const float* b3  = (const float*)d_in[9];   // (2,)
    float* out = (float*)d_out;

    int wadj = (out_size >= NBATCH * NPAIR * 3) ? 1 : 0;

    prep_kernel<<<1, 128>>>(Wp, bp, W1, b1);
    gpn_kernel<<<NBATCH / BPB, NTHREADS>>>(pos, ori, W2, b2, W3, b3, out, wadj);
}

// round 13
// speedup vs baseline: 3.4241x; 1.0486x over previous
#include <cuda_runtime.h>

#define NBATCH 16384
#define NN 10
#define NPAIR (NN * NN)
#define BPB 8                        // batches per block
#define ROWS (BPB * NN)              // 80 rows per block
#define NTHREADS (2 * ROWS)          // 160 threads: 2 lanes per row (q-split)
#define VSTRIDE 12                   // padded per-batch v stride (float4 alignment)

typedef unsigned long long ull;

// Fused front-end weights: u_i = x_i @ A + ab,  v_j = x_j @ Bm + bb
// where A = Wp @ W1[:16], Bm = Wp @ W1[16:], ab = bp@W1[:16] + b1, bb = bp@W1[16:]
__device__ float g_A[96];
__device__ float g_Bm[96];
__device__ float g_ab[32];
__device__ float g_bb[32];

__global__ void prep_kernel(const float* __restrict__ Wp, const float* __restrict__ bp,
                            const float* __restrict__ W1, const float* __restrict__ b1) {
    int t = threadIdx.x;
    if (t < 96) {
        int r = t >> 5, c = t & 31;
        float a = 0.f, bm = 0.f;
#pragma unroll
        for (int m = 0; m < 16; m++) {
            float w = Wp[r * 16 + m];
            a  = fmaf(w, W1[m * 32 + c], a);
            bm = fmaf(w, W1[(16 + m) * 32 + c], bm);
        }
        g_A[t]  = a;
        g_Bm[t] = bm;
    } else if (t < 128) {
        int c = t - 96;
        float a = b1[c], bm = 0.f;
#pragma unroll
        for (int m = 0; m < 16; m++) {
            float w = bp[m];
            a  = fmaf(w, W1[m * 32 + c], a);
            bm = fmaf(w, W1[(16 + m) * 32 + c], bm);
        }
        g_ab[c] = a;
        g_bb[c] = bm;
    }
}

__device__ __forceinline__ ull pack2(float a, float b) {
    ull p;
    asm("mov.b64 %0, {%1, %2};" : "=l"(p)
        : "r"(__float_as_uint(a)), "r"(__float_as_uint(b)));
    return p;
}
__device__ __forceinline__ ull add2(ull a, ull b) {
    ull r; asm("add.rn.f32x2 %0, %1, %2;" : "=l"(r) : "l"(a), "l"(b)); return r;
}
__device__ __forceinline__ ull fma2r(ull a, ull b, ull c) {
    ull r; asm("fma.rn.f32x2 %0, %1, %2, %3;" : "=l"(r) : "l"(a), "l"(b), "l"(c)); return r;
}
__device__ __forceinline__ void fma2(ull& acc, ull a, ull b) {
    asm("fma.rn.f32x2 %0, %1, %2, %0;" : "+l"(acc) : "l"(a), "l"(b));
}
__device__ __forceinline__ void unpack2(ull p, float& lo, float& hi) {
    unsigned int a, b;
    asm("mov.b64 {%0, %1}, %2;" : "=r"(a), "=r"(b) : "l"(p));
    lo = __uint_as_float(a); hi = __uint_as_float(b);
}
__device__ __forceinline__ float lrelu(float x) { return fmaxf(x, 0.2f * x); }

__global__ void __launch_bounds__(NTHREADS, 6)
gpn_kernel(const float* __restrict__ pos, const float* __restrict__ ori,
           const float* __restrict__ W2, const float* __restrict__ b2,
           const float* __restrict__ W3, const float* __restrict__ b3,
           float* __restrict__ out, int wadj)
{
    __shared__ ull   us[32 * ROWS];              // (u,u) dup, [c][row]     20480 B
    __shared__ float vs[32 * BPB * VSTRIDE];     // v, [c][b*12 + j]        12288 B
    __shared__ ull   W2d[32 * 8];                // 0.4*W2 duplicated f32x2  2048 B
    __shared__ ull   b2d[8];
    __shared__ float W3s[16], b3s[2];
    __shared__ float xs0[ROWS], xs1[ROWS], xs2[ROWS];
    __shared__ float wA[96], wB[96], wab[32], wbb[32];

    int t = threadIdx.x;

    // ---- stage fused weights + node features ----
    if (t < 96)       { wA[t] = g_A[t]; wB[t] = g_Bm[t]; }
    else if (t < 128) { int c = t - 96; wab[c] = g_ab[c]; wbb[c] = g_bb[c]; }
    if (t < ROWS) {
        int g = blockIdx.x * ROWS + t;
        float2 p = reinterpret_cast<const float2*>(pos)[g];
        xs0[t] = p.x; xs1[t] = p.y; xs2[t] = ori[g];
    }
    // W2 pre-scaled by 0.4: lrelu(t) = 0.4*(1.5t + |t|), the 0.4 folds into W2
    for (int i0 = t; i0 < 256; i0 += NTHREADS) {
        float w = 0.4f * W2[i0];
        W2d[i0] = pack2(w, w);
    }
    if (t < 8)  { float w = b2[t]; b2d[t] = pack2(w, w); }
    if (t < 16) W3s[t] = W3[t];
    if (t < 2)  b3s[t] = b3[t];
    __syncthreads();

    // ---- phase 1: compute u (duplicated) and v transposed ----
    for (int idx = t; idx < 32 * ROWS; idx += NTHREADS) {
        int c = idx / ROWS, node = idx - c * ROWS;
        float x0 = xs0[node], x1 = xs1[node], x2 = xs2[node];
        int nb = node / NN, ni = node - nb * NN;
        float u =
            fmaf(x0, wA[c], fmaf(x1, wA[32 + c], fmaf(x2, wA[64 + c], wab[c])));
        us[c * ROWS + node] = pack2(u, u);
        vs[c * (BPB * VSTRIDE) + nb * VSTRIDE + ni] =
            fmaf(x0, wB[c], fmaf(x1, wB[32 + c], fmaf(x2, wB[64 + c], wbb[c])));
    }
    __syncthreads();

    // ---- phase 2: lanes (2m, 2m+1) co-own row (b, i); each does 4 of 8 q ----
    int row  = t >> 1;            // 0..79
    int half = t & 1;             // q-half: 0 -> q 0..3, 1 -> q 4..7
    int b = row / NN;
    int i = row - b * NN;

    const ull K15 = 0x3FC000003FC00000ULL;  // (1.5f, 1.5f)
    const ull KAB = 0x7FFFFFFF7FFFFFFFULL;  // abs mask

    ull acc[5][4];
#pragma unroll
    for (int g = 0; g < 5; g++)
#pragma unroll
        for (int q = 0; q < 4; q++)
            acc[g][q] = b2d[half * 4 + q];

    const ull*  usp = us + row;
    const char* vsp = (const char*)(vs + b * VSTRIDE);
    const ull*  w2p = W2d + half * 4;

    // software-pipelined mainloop: prefetch next u/v (longest dependence
    // chains) while computing c; W2 rows load in-iteration (covered by the
    // activation latency, and dropping them from the prefetch set keeps the
    // kernel at 64 regs -> 6 CTAs/SM).
    ull uu = usp[0];
    ulonglong2 v01 = *reinterpret_cast<const ulonglong2*>(vsp);
    ulonglong2 v23 = *reinterpret_cast<const ulonglong2*>(vsp + 16);
    ull        v4  = *reinterpret_cast<const ull*>(vsp + 32);

#pragma unroll
    for (int c = 0; c < 32; c++) {
        ull cuu = uu;
        ull vp[5] = { v01.x, v01.y, v23.x, v23.y, v4 };

        if (c < 31) {
            uu = usp[(c + 1) * ROWS];
            const char* nv = vsp + (c + 1) * (BPB * VSTRIDE * 4);
            v01 = *reinterpret_cast<const ulonglong2*>(nv);
            v23 = *reinterpret_cast<const ulonglong2*>(nv + 16);
            v4  = *reinterpret_cast<const ull*>(nv + 32);
        }

        // p = 1.5t + |t| ; lrelu(t)*W2 == p*(0.4*W2)
        ull s[5];
#pragma unroll
        for (int g = 0; g < 5; g++) {
            ull t2 = add2(cuu, vp[g]);
            s[g] = fma2r(t2, K15, t2 & KAB);
        }

        const ull* w = w2p + c * 8;
        ulonglong2 cw01 = *reinterpret_cast<const ulonglong2*>(w);
        ulonglong2 cw23 = *reinterpret_cast<const ulonglong2*>(w + 2);
#pragma unroll
        for (int g = 0; g < 5; g++) {
            fma2(acc[g][0], s[g], cw01.x);
            fma2(acc[g][1], s[g], cw01.y);
            fma2(acc[g][2], s[g], cw23.x);
            fma2(acc[g][3], s[g], cw23.y);
        }
    }

    // ---- epilogue: partial W3 head over own 4 q's, butterfly-sum with lane
    //      partner, then each lane stores its j of every group ----
    size_t rowbase = (size_t)(blockIdx.x * BPB + b) * NPAIR + (size_t)i * NN;
    float* edge = out + rowbase * 2;
    float* adj  = out + (size_t)NBATCH * NPAIR * 2 + rowbase;

    const float* w3p = W3s + half * 8;
    float bias0 = (half == 0) ? b3s[0] : 0.f;
    float bias1 = (half == 0) ? b3s[1] : 0.f;

#pragma unroll
    for (int g = 0; g < 5; g++) {
        float eA0 = bias0, eA1 = bias1, eB0 = bias0, eB1 = bias1;
#pragma unroll
        for (int q = 0; q < 4; q++) {
            float h0, h1;
            unpack2(acc[g][q], h0, h1);
            h0 = lrelu(h0); h1 = lrelu(h1);
            float w0 = w3p[2 * q], w1 = w3p[2 * q + 1];
            eA0 = fmaf(h0, w0, eA0); eA1 = fmaf(h0, w1, eA1);
            eB0 = fmaf(h1, w0, eB0); eB1 = fmaf(h1, w1, eB1);
        }
        // complete across the two q-halves (lanes 2m <-> 2m+1)
        eA0 += __shfl_xor_sync(0xFFFFFFFF, eA0, 1);
        eA1 += __shfl_xor_sync(0xFFFFFFFF, eA1, 1);
        eB0 += __shfl_xor_sync(0xFFFFFFFF, eB0, 1);
        eB1 += __shfl_xor_sync(0xFFFFFFFF, eB1, 1);

        // lane half stores pair j = 2g + half at output slot s(j)
        int j  = 2 * g + half;
        int sj = (j == i) ? 0 : ((j < i) ? j + 1 : j);
        float2 ev;
        ev.x = half ? eB0 : eA0;
        ev.y = half ? eB1 : eA1;
        reinterpret_cast<float2*>(edge)[sj] = ev;
        if (wadj)
            adj[sj] = (ev.y > ev.x) ? 1.f : 0.f;   // argmax of 2; ties -> 0
    }
}

extern "C" void kernel_launch(void* const* d_in, const int* in_sizes, int n_in,
                              void* d_out, int out_size) {
    const float* pos = (const float*)d_in[0];   // (B, N, 2)
    const float* ori = (const float*)d_in[1];   // (B, N, 1)
    const float* Wp  = (const float*)d_in[2];   // (3, 16)
    const float* bp  = (const float*)d_in[3];   // (16,)
    const float* W1  = (const float*)d_in[4];   // (32, 32)
    const float* b1  = (const float*)d_in[5];   // (32,)
    const float* W2  = (const float*)d_in[6];   // (32, 8)
    const float* b2  = (const float*)d_in[7];   // (8,)
    const float* W3  = (const float*)d_in[8];   // (8, 2)
    const float* b3  = (const float*)d_in[9];   // (2,)
    float* out = (float*)d_out;

    int wadj = (out_size >= NBATCH * NPAIR * 3) ? 1 : 0;

    prep_kernel<<<1, 128>>>(Wp, bp, W1, b1);
    gpn_kernel<<<NBATCH / BPB, NTHREADS>>>(pos, ori, W2, b2, W3, b3, out, wadj);
}

// round 14
// speedup vs baseline: 3.5528x; 1.0376x over previous
#include <cuda_runtime.h>

#define NBATCH 16384
#define NN 10
#define NPAIR (NN * NN)
#define BPB 8                        // batches per block
#define ROWS (BPB * NN)              // 80 rows per block
#define NTHREADS (2 * ROWS)          // 160 threads: 2 lanes per row
#define VSTRIDE 12                   // padded per-batch v stride (float4 alignment)
#define VROWB (BPB * VSTRIDE * 4)    // bytes per c-row of vs = 384

typedef unsigned long long ull;

__device__ __forceinline__ ull pack2(float a, float b) {
    ull p;
    asm("mov.b64 %0, {%1, %2};" : "=l"(p)
        : "r"(__float_as_uint(a)), "r"(__float_as_uint(b)));
    return p;
}
__device__ __forceinline__ ull add2(ull a, ull b) {
    ull r; asm("add.rn.f32x2 %0, %1, %2;" : "=l"(r) : "l"(a), "l"(b)); return r;
}
__device__ __forceinline__ ull fma2r(ull a, ull b, ull c) {
    ull r; asm("fma.rn.f32x2 %0, %1, %2, %3;" : "=l"(r) : "l"(a), "l"(b), "l"(c)); return r;
}
__device__ __forceinline__ void fma2(ull& acc, ull a, ull b) {
    asm("fma.rn.f32x2 %0, %1, %2, %0;" : "+l"(acc) : "l"(a), "l"(b));
}
__device__ __forceinline__ void unpack2(ull p, float& lo, float& hi) {
    unsigned int a, b;
    asm("mov.b64 {%0, %1}, %2;" : "=r"(a), "=r"(b) : "l"(p));
    lo = __uint_as_float(a); hi = __uint_as_float(b);
}
__device__ __forceinline__ float lrelu(float x) { return fmaxf(x, 0.2f * x); }

__global__ void __launch_bounds__(NTHREADS, 6)
gpn_kernel(const float* __restrict__ pos, const float* __restrict__ ori,
           const float* __restrict__ Wp,  const float* __restrict__ bp,
           const float* __restrict__ W1,  const float* __restrict__ b1,
           const float* __restrict__ W2,  const float* __restrict__ b2,
           const float* __restrict__ W3,  const float* __restrict__ b3,
           float* __restrict__ out, int wadj)
{
    __shared__ ull   us[32 * ROWS];              // (u,u) dup, [c][row]     20480 B
    __shared__ float vs[32 * BPB * VSTRIDE];     // v, [c][b*12 + j]        12288 B
    __shared__ ull   W2d[32 * 8];                // 0.4*W2 duplicated f32x2  2048 B
    __shared__ ull   b2d[8];
    __shared__ float W3s[16], b3s[2];
    __shared__ float xs0[ROWS], xs1[ROWS], xs2[ROWS];
    __shared__ float wA[96], wB[96], wab[32], wbb[32];

    int t = threadIdx.x;

    // ---- stage: fuse front-end weights in-block (prep kernel folded in) ----
    // A = Wp @ W1[:16], Bm = Wp @ W1[16:], ab = bp@W1[:16]+b1, bb = bp@W1[16:]
    if (t < 96) {
        int r = t >> 5, c = t & 31;
        float a = 0.f, bm = 0.f;
#pragma unroll
        for (int m = 0; m < 16; m++) {
            float w = Wp[r * 16 + m];
            a  = fmaf(w, W1[m * 32 + c], a);
            bm = fmaf(w, W1[(16 + m) * 32 + c], bm);
        }
        wA[t] = a; wB[t] = bm;
    } else if (t < 128) {
        int c = t - 96;
        float a = b1[c], bm = 0.f;
#pragma unroll
        for (int m = 0; m < 16; m++) {
            float w = bp[m];
            a  = fmaf(w, W1[m * 32 + c], a);
            bm = fmaf(w, W1[(16 + m) * 32 + c], bm);
        }
        wab[c] = a; wbb[c] = bm;
    }
    if (t < ROWS) {
        int g = blockIdx.x * ROWS + t;
        float2 p = reinterpret_cast<const float2*>(pos)[g];
        xs0[t] = p.x; xs1[t] = p.y; xs2[t] = ori[g];
    }
    // W2 pre-scaled by 0.4: lrelu(t) = 0.4*(1.5t + |t|), the 0.4 folds into W2
    for (int i0 = t; i0 < 256; i0 += NTHREADS) {
        float w = 0.4f * W2[i0];
        W2d[i0] = pack2(w, w);
    }
    if (t < 8)  { float w = b2[t]; b2d[t] = pack2(w, w); }
    if (t < 16) W3s[t] = W3[t];
    if (t < 2)  b3s[t] = b3[t];
    __syncthreads();

    // ---- phase 1: compute u (duplicated) and v transposed ----
    for (int idx = t; idx < 32 * ROWS; idx += NTHREADS) {
        int c = idx / ROWS, node = idx - c * ROWS;
        float x0 = xs0[node], x1 = xs1[node], x2 = xs2[node];
        int nb = node / NN, ni = node - nb * NN;
        float u =
            fmaf(x0, wA[c], fmaf(x1, wA[32 + c], fmaf(x2, wA[64 + c], wab[c])));
        us[c * ROWS + node] = pack2(u, u);
        vs[c * (BPB * VSTRIDE) + nb * VSTRIDE + ni] =
            fmaf(x0, wB[c], fmaf(x1, wB[32 + c], fmaf(x2, wB[64 + c], wbb[c])));
    }
    __syncthreads();

    // ---- phase 2: lanes (2m, 2m+1) co-own row (b, i) ----
    // Lane `half` computes activated groups own = {2*half, 2*half+1} plus g4;
    // the other two groups arrive via shfl_xor from the partner lane.
    // Accumulators are kept in LANE-LOCAL group order [own0, own1, recv0,
    // recv1, g4]; the epilogue resolves the permutation (global group of
    // local lg is lg ^ (half*2) for lg<4).
    int row  = t >> 1;            // 0..79
    int half = t & 1;
    int b = row / NN;
    int i = row - b * NN;

    const ull K15 = 0x3FC000003FC00000ULL;  // (1.5f, 1.5f)
    const ull KAB = 0x7FFFFFFF7FFFFFFFULL;  // abs mask

    ull acc[5][4];
#pragma unroll
    for (int g = 0; g < 5; g++)
#pragma unroll
        for (int q = 0; q < 4; q++)
            acc[g][q] = b2d[half * 4 + q];

    const ull*  usp = us + row;
    const char* vbase = (const char*)(vs + b * VSTRIDE);
    int voff = half * 16;                    // own v quad: bytes [voff, voff+16)
    const ull* w2p = W2d + half * 4;

    // prefetch c=0
    ull uu = usp[0];
    ulonglong2 vo = *reinterpret_cast<const ulonglong2*>(vbase + voff);
    ull        v4 = *reinterpret_cast<const ull*>(vbase + 32);

#pragma unroll
    for (int c = 0; c < 32; c++) {
        ull cuu = uu;
        ulonglong2 cvo = vo;
        ull cv4 = v4;

        if (c < 31) {
            uu = usp[(c + 1) * ROWS];
            const char* nv = vbase + (c + 1) * VROWB;
            vo = *reinterpret_cast<const ulonglong2*>(nv + voff);
            v4 = *reinterpret_cast<const ull*>(nv + 32);
        }

        // own activations: p = 1.5t + |t| ; lrelu(t)*W2 == p*(0.4*W2)
        ull t0 = add2(cuu, cvo.x);
        ull sA = fma2r(t0, K15, t0 & KAB);
        ull t1 = add2(cuu, cvo.y);
        ull sB = fma2r(t1, K15, t1 & KAB);
        ull t4 = add2(cuu, cv4);
        ull s4 = fma2r(t4, K15, t4 & KAB);

        // exchange with partner lane (identical bits to local recompute)
        ull rA = __shfl_xor_sync(0xFFFFFFFF, sA, 1);
        ull rB = __shfl_xor_sync(0xFFFFFFFF, sB, 1);

        const ull* w = w2p + c * 8;
        ulonglong2 cw01 = *reinterpret_cast<const ulonglong2*>(w);
        ulonglong2 cw23 = *reinterpret_cast<const ulonglong2*>(w + 2);

        ull sl[5] = { sA, sB, rA, rB, s4 };
#pragma unroll
        for (int g = 0; g < 5; g++) {
            fma2(acc[g][0], sl[g], cw01.x);
            fma2(acc[g][1], sl[g], cw01.y);
            fma2(acc[g][2], sl[g], cw23.x);
            fma2(acc[g][3], sl[g], cw23.y);
        }
    }

    // ---- epilogue ----
    size_t rowbase = (size_t)(blockIdx.x * BPB + b) * NPAIR + (size_t)i * NN;
    float* edge = out + rowbase * 2;
    float* adj  = out + (size_t)NBATCH * NPAIR * 2 + rowbase;

    const float* w3p = W3s + half * 8;
    float bias0 = (half == 0) ? b3s[0] : 0.f;
    float bias1 = (half == 0) ? b3s[1] : 0.f;

    // partial W3 head per local group (own 4 q's)
    float eA0[5], eA1[5], eB0[5], eB1[5];
#pragma unroll
    for (int lg = 0; lg < 5; lg++) {
        float a0 = bias0, a1 = bias1, c0 = bias0, c1 = bias1;
#pragma unroll
        for (int q = 0; q < 4; q++) {
            float h0, h1;
            unpack2(acc[lg][q], h0, h1);
            h0 = lrelu(h0); h1 = lrelu(h1);
            float w0 = w3p[2 * q], w1 = w3p[2 * q + 1];
            a0 = fmaf(h0, w0, a0); a1 = fmaf(h0, w1, a1);
            c0 = fmaf(h1, w0, c0); c1 = fmaf(h1, w1, c1);
        }
        eA0[lg] = a0; eA1[lg] = a1; eB0[lg] = c0; eB1[lg] = c1;
    }

    // butterfly: partner's partial of the SAME global group lives at partner's
    // local index lg^2 (lg<4) / 4 (lg==4); exchanging eX[lg^2] pairs them.
#pragma unroll
    for (int lg = 0; lg < 5; lg++) {
        int pl = (lg < 4) ? (lg ^ 2) : 4;
        float fA0 = eA0[lg] + __shfl_xor_sync(0xFFFFFFFF, eA0[pl], 1);
        float fA1 = eA1[lg] + __shfl_xor_sync(0xFFFFFFFF, eA1[pl], 1);
        float fB0 = eB0[lg] + __shfl_xor_sync(0xFFFFFFFF, eB0[pl], 1);
        float fB1 = eB1[lg] + __shfl_xor_sync(0xFFFFFFFF, eB1[pl], 1);

        // global group of local lg; lane stores element `half` of it
        int G = (lg < 4) ? (lg ^ (half << 1)) : 4;
        int j = 2 * G + half;
        int sj = (j == i) ? 0 : ((j < i) ? j + 1 : j);
        float2 ev;
        ev.x = half ? fB0 : fA0;
        ev.y = half ? fB1 : fA1;
        reinterpret_cast<float2*>(edge)[sj] = ev;
        if (wadj)
            adj[sj] = (ev.y > ev.x) ? 1.f : 0.f;   // argmax of 2; ties -> 0
    }
}

extern "C" void kernel_launch(void* const* d_in, const int* in_sizes, int n_in,
                              void* d_out, int out_size) {
    const float* pos = (const float*)d_in[0];   // (B, N, 2)
    const float* ori = (const float*)d_in[1];   // (B, N, 1)
    const float* Wp  = (const float*)d_in[2];   // (3, 16)
    const float* bp  = (const float*)d_in[3];   // (16,)
    const float* W1  = (const float*)d_in[4];   // (32, 32)
    const float* b1  = (const float*)d_in[5];   // (32,)
    const float* W2  = (const float*)d_in[6];   // (32, 8)
    const float* b2  = (const float*)d_in[7];   // (8,)
    const float* W3  = (const float*)d_in[8];   // (8, 2)
    const float* b3  = (const float*)d_in[9];   // (2,)
    float* out = (float*)d_out;

    int wadj = (out_size >= NBATCH * NPAIR * 3) ? 1 : 0;

    gpn_kernel<<<NBATCH / BPB, NTHREADS>>>(pos, ori, Wp, bp, W1, b1,
                                           W2, b2, W3, b3, out, wadj);
}